// round 1
// baseline (speedup 1.0000x reference)
#include <cuda_runtime.h>
#include <math.h>

// ---------------- problem constants ----------------
#define NTOK   21760            // tokens per batch
#define BATCH  2
#define NQ     (NTOK*BATCH)     // 43520 rows
#define DIM    256
#define NHEAD  8
#define DHEAD  32
#define NLAY   6
#define DFFN   1024
#define QOUT   (NQ*DIM)         // 11,141,120 floats of q output

// level tables
__device__ __constant__ int   c_LW[4] = {128, 64, 32, 16};
__device__ __constant__ int   c_LS[4] = {0, 16384, 20480, 21504};
__constant__ float c_tail[12] = {128.f,128.f,64.f,64.f,32.f,32.f,16.f,16.f,
                                 0.f,16384.f,20480.f,21504.f};

// ---------------- scratch (device globals; allocation-free) ----------------
__device__ float g_q   [NQ*DIM];
__device__ float g_posf[NQ*DIM];
__device__ float g_n   [NQ*DIM];
__device__ float g_qin [NQ*DIM];
__device__ float g_val [NQ*DIM];
__device__ float g_off [NQ*DIM];
__device__ float g_attn[NQ*128];
__device__ float g_samp[NQ*DIM];
__device__ float g_h1  [NQ*DFFN];

// ---------------- init: [B,D,H,W] -> token-major [B*N, D] (+ level embed) ----
__global__ void __launch_bounds__(256)
transpose_level(const float* __restrict__ src, float* __restrict__ dst,
                int HW, int start, const float* __restrict__ le)
{
    __shared__ float tile[32][33];
    int b  = blockIdx.z;
    int p0 = blockIdx.x * 32;
    int d0 = blockIdx.y * 32;
    int tx = threadIdx.x;      // 0..31
    int ty = threadIdx.y;      // 0..7

    const float* s = src + ((size_t)b * DIM + d0) * HW + p0;
    #pragma unroll
    for (int i = ty; i < 32; i += 8)
        tile[i][tx] = s[(size_t)i * HW + tx];          // tile[d][p]
    __syncthreads();
    #pragma unroll
    for (int i = ty; i < 32; i += 8) {
        float v = tile[tx][i];                          // d=d0+tx, p=p0+i
        if (le) v += le[d0 + tx];
        dst[((size_t)b * NTOK + start + p0 + i) * DIM + d0 + tx] = v;
    }
}

// ---------------- RMSNorm (warp per row); optionally also qin = n + posf -----
__global__ void __launch_bounds__(256)
rms_kernel(const float* __restrict__ x, const float* __restrict__ g,
           const float* __restrict__ posf, float* __restrict__ out_n,
           float* __restrict__ out_qin)
{
    int warp = threadIdx.x >> 5, lane = threadIdx.x & 31;
    int row  = blockIdx.x * 8 + warp;
    const float* xr = x + (size_t)row * DIM;

    float4 v0 = *(const float4*)(xr + lane * 4);
    float4 v1 = *(const float4*)(xr + 128 + lane * 4);
    float s = v0.x*v0.x + v0.y*v0.y + v0.z*v0.z + v0.w*v0.w
            + v1.x*v1.x + v1.y*v1.y + v1.z*v1.z + v1.w*v1.w;
    #pragma unroll
    for (int o = 16; o; o >>= 1) s += __shfl_xor_sync(0xffffffffu, s, o);
    float scale = rsqrtf(s * (1.0f / 256.0f) + 1e-6f);

    float4 ga = *(const float4*)(g + lane * 4);
    float4 gb = *(const float4*)(g + 128 + lane * 4);
    float4 n0 = make_float4(v0.x*scale*ga.x, v0.y*scale*ga.y,
                            v0.z*scale*ga.z, v0.w*scale*ga.w);
    float4 n1 = make_float4(v1.x*scale*gb.x, v1.y*scale*gb.y,
                            v1.z*scale*gb.z, v1.w*scale*gb.w);
    float* nr = out_n + (size_t)row * DIM;
    *(float4*)(nr + lane * 4)       = n0;
    *(float4*)(nr + 128 + lane * 4) = n1;

    if (out_qin) {
        const float* pr = posf + (size_t)row * DIM;
        float4 p0 = *(const float4*)(pr + lane * 4);
        float4 p1 = *(const float4*)(pr + 128 + lane * 4);
        float4 q0 = make_float4(n0.x+p0.x, n0.y+p0.y, n0.z+p0.z, n0.w+p0.w);
        float4 q1 = make_float4(n1.x+p1.x, n1.y+p1.y, n1.z+p1.z, n1.w+p1.w);
        float* qr = out_qin + (size_t)row * DIM;
        *(float4*)(qr + lane * 4)       = q0;
        *(float4*)(qr + 128 + lane * 4) = q1;
    }
}

// ---------------- SGEMM: C[M,Nc] = A[M,K] @ B[Nc,K]^T + bias, fused epilogues
// EPI 0: C = v
// EPI 1: C[m,n] += ls[n] * v        (residual, C preloaded = q)
// EPI 2: C = silu(v)
// EPI 3: C = v * other[m,n]         (other may alias C)
template<int EPI>
__global__ void __launch_bounds__(256)
sgemm(int M, int Nc, int K,
      const float* __restrict__ A, const float* __restrict__ B,
      const float* __restrict__ bias, float* __restrict__ C,
      const float* __restrict__ ls, const float* __restrict__ other)
{
    constexpr int BM = 128, BN = 128, BK = 16;
    __shared__ float As[BK][BM + 4];
    __shared__ float Bs[BK][BN + 4];

    int tid = threadIdx.x;
    int bm = blockIdx.y, bn = blockIdx.x;
    int tx = tid & 15, ty = tid >> 4;

    const float* Ab = A + (size_t)bm * BM * K;
    const float* Bb = B + (size_t)bn * BN * K;

    float acc[8][8];
    #pragma unroll
    for (int i = 0; i < 8; i++)
        #pragma unroll
        for (int j = 0; j < 8; j++) acc[i][j] = 0.f;

    for (int kk = 0; kk < K; kk += BK) {
        #pragma unroll
        for (int i = 0; i < 2; i++) {
            int l = tid + 256 * i;
            int r = l >> 2, c = l & 3;
            float4 av = *(const float4*)(Ab + (size_t)r * K + kk + c * 4);
            As[c*4+0][r] = av.x; As[c*4+1][r] = av.y;
            As[c*4+2][r] = av.z; As[c*4+3][r] = av.w;
            float4 bv = *(const float4*)(Bb + (size_t)r * K + kk + c * 4);
            Bs[c*4+0][r] = bv.x; Bs[c*4+1][r] = bv.y;
            Bs[c*4+2][r] = bv.z; Bs[c*4+3][r] = bv.w;
        }
        __syncthreads();
        #pragma unroll
        for (int k = 0; k < BK; k++) {
            float ra[8], rb[8];
            *(float4*)(ra)     = *(const float4*)&As[k][ty * 8];
            *(float4*)(ra + 4) = *(const float4*)&As[k][ty * 8 + 4];
            *(float4*)(rb)     = *(const float4*)&Bs[k][tx * 8];
            *(float4*)(rb + 4) = *(const float4*)&Bs[k][tx * 8 + 4];
            #pragma unroll
            for (int i = 0; i < 8; i++)
                #pragma unroll
                for (int j = 0; j < 8; j++)
                    acc[i][j] = fmaf(ra[i], rb[j], acc[i][j]);
        }
        __syncthreads();
    }

    int row0 = bm * BM + ty * 8, col0 = bn * BN + tx * 8;
    #pragma unroll
    for (int i = 0; i < 8; i++) {
        float* Crow = C + (size_t)(row0 + i) * Nc + col0;
        #pragma unroll
        for (int j = 0; j < 8; j++) {
            float v = acc[i][j] + bias[col0 + j];
            if (EPI == 1)      Crow[j] = Crow[j] + ls[col0 + j] * v;
            else if (EPI == 2) Crow[j] = v / (1.f + __expf(-v));
            else if (EPI == 3) Crow[j] = v * other[(size_t)(row0 + i) * Nc + col0 + j];
            else               Crow[j] = v;
        }
    }
}

// ---------------- deformable sampling (block=token, warp=head, lane=channel) -
__global__ void __launch_bounds__(256)
msda_kernel(const float* __restrict__ off, const float* __restrict__ attnlog,
            const float* __restrict__ value, float* __restrict__ samp)
{
    int row  = blockIdx.x;               // 0..NQ-1
    int h    = threadIdx.x >> 5;
    int lane = threadIdx.x & 31;
    int b = row / NTOK;
    int n = row - b * NTOK;

    int lvl = (n >= 21504) ? 3 : (n >= 20480) ? 2 : (n >= 16384) ? 1 : 0;
    int Wq  = c_LW[lvl];
    int li  = n - c_LS[lvl];
    int iy  = li / Wq, ix = li - iy * Wq;
    float refx = (ix + 0.5f) / (float)Wq;
    float refy = (iy + 0.5f) / (float)Wq;       // H==W per level

    // softmax over 16 (per-lane redundant, L1-broadcast loads)
    const float* al = attnlog + (size_t)row * 128 + h * 16;
    float lg[16];
    float m = -1e30f;
    #pragma unroll
    for (int j = 0; j < 16; j++) { lg[j] = al[j]; m = fmaxf(m, lg[j]); }
    float s = 0.f;
    #pragma unroll
    for (int j = 0; j < 16; j++) { lg[j] = __expf(lg[j] - m); s += lg[j]; }
    float inv = 1.f / s;

    const float* op = off + (size_t)row * 256 + h * 32;
    const float* vb = value + ((size_t)b * NTOK) * 256 + h * 32 + lane;
    float acc = 0.f;

    #pragma unroll
    for (int l = 0; l < 4; l++) {
        int Wl = c_LW[l], st = c_LS[l];
        float fW = (float)Wl;
        #pragma unroll
        for (int p = 0; p < 4; p++) {
            float ox = op[l * 8 + p * 2 + 0];
            float oy = op[l * 8 + p * 2 + 1];
            float xx = (refx + ox / fW) * fW - 0.5f;
            float yy = (refy + oy / fW) * fW - 0.5f;   // H==W
            float x0f = floorf(xx), y0f = floorf(yy);
            int x0 = (int)x0f, y0 = (int)y0f;
            float fx = xx - x0f, fy = yy - y0f;
            float aw  = lg[l * 4 + p] * inv;
            float w00 = (1.f - fx) * (1.f - fy) * aw;
            float w10 = fx * (1.f - fy) * aw;
            float w01 = (1.f - fx) * fy * aw;
            float w11 = fx * fy * aw;
            bool vx0 = (x0 >= 0)     && (x0 < Wl);
            bool vx1 = (x0 + 1 >= 0) && (x0 + 1 < Wl);
            bool vy0 = (y0 >= 0)     && (y0 < Wl);
            bool vy1 = (y0 + 1 >= 0) && (y0 + 1 < Wl);
            if (vx0 && vy0) acc += w00 * vb[(size_t)(st + y0     * Wl + x0    ) * 256];
            if (vx1 && vy0) acc += w10 * vb[(size_t)(st + y0     * Wl + x0 + 1) * 256];
            if (vx0 && vy1) acc += w01 * vb[(size_t)(st + (y0+1) * Wl + x0    ) * 256];
            if (vx1 && vy1) acc += w11 * vb[(size_t)(st + (y0+1) * Wl + x0 + 1) * 256];
        }
    }
    samp[(size_t)row * 256 + h * 32 + lane] = acc;
}

// ---------------- output copy (+ value-cast int tail if present) -------------
__global__ void write_out(const float* __restrict__ q, float* __restrict__ out,
                          int out_size)
{
    for (int i = blockIdx.x * blockDim.x + threadIdx.x; i < out_size;
         i += gridDim.x * blockDim.x) {
        float v;
        if (i < QOUT) v = q[i];
        else { int j = i - QOUT; v = (j < 12) ? c_tail[j] : 0.f; }
        out[i] = v;
    }
}

// =============================== launcher ====================================
extern "C" void kernel_launch(void* const* d_in, const int* in_sizes, int n_in,
                              void* d_out, int out_size)
{
    (void)n_in;
    // src/pos ordering: interleaved (setup_inputs dict) vs grouped (signature)
    const float* src[4];
    const float* pos[4];
    bool interleaved = (in_sizes[1] == in_sizes[0]);
    for (int i = 0; i < 4; i++) {
        if (interleaved) { src[i] = (const float*)d_in[2*i];
                           pos[i] = (const float*)d_in[2*i+1]; }
        else             { src[i] = (const float*)d_in[i];
                           pos[i] = (const float*)d_in[4+i]; }
    }
    const float* level_embed = (const float*)d_in[8];
    const float* W_off  = (const float*)d_in[9];
    const float* b_off  = (const float*)d_in[10];
    const float* W_attn = (const float*)d_in[11];
    const float* b_attn = (const float*)d_in[12];
    const float* W_val  = (const float*)d_in[13];
    const float* b_val  = (const float*)d_in[14];
    const float* W_out  = (const float*)d_in[15];
    const float* b_out  = (const float*)d_in[16];
    const float* g_na   = (const float*)d_in[17];
    const float* g_nf   = (const float*)d_in[18];
    const float* ls_a   = (const float*)d_in[19];
    const float* ls_f   = (const float*)d_in[20];
    const float* W1     = (const float*)d_in[21];
    const float* b1     = (const float*)d_in[22];
    const float* W3     = (const float*)d_in[23];
    const float* b3     = (const float*)d_in[24];
    const float* W2     = (const float*)d_in[25];
    const float* b2     = (const float*)d_in[26];

    float *q, *posf, *nbuf, *qin, *val, *offb, *attnb, *sampb, *h1;
    cudaGetSymbolAddress((void**)&q,     g_q);
    cudaGetSymbolAddress((void**)&posf,  g_posf);
    cudaGetSymbolAddress((void**)&nbuf,  g_n);
    cudaGetSymbolAddress((void**)&qin,   g_qin);
    cudaGetSymbolAddress((void**)&val,   g_val);
    cudaGetSymbolAddress((void**)&offb,  g_off);
    cudaGetSymbolAddress((void**)&attnb, g_attn);
    cudaGetSymbolAddress((void**)&sampb, g_samp);
    cudaGetSymbolAddress((void**)&h1,    g_h1);

    const int HWs[4]    = {16384, 4096, 1024, 256};
    const int starts[4] = {0, 16384, 20480, 21504};

    // init: build q and posf token-major
    for (int l = 0; l < 4; l++) {
        dim3 grid(HWs[l] / 32, DIM / 32, BATCH), blk(32, 8);
        transpose_level<<<grid, blk>>>(src[l], q,    HWs[l], starts[l], nullptr);
        transpose_level<<<grid, blk>>>(pos[l], posf, HWs[l], starts[l],
                                       level_embed + l * DIM);
    }

    const int M = NQ;
    dim3 g2(2, M / 128), g1(1, M / 128), g8(8, M / 128);

    for (int i = 0; i < NLAY; i++) {
        // pre-attn norm: n = rmsnorm(q, g_na), qin = n + posf
        rms_kernel<<<NQ / 8, 256>>>(q, g_na + i * DIM, posf, nbuf, qin);
        // projections
        sgemm<0><<<g2, 256>>>(M, 256, 256, nbuf, W_val + i * 65536,
                              b_val + i * 256, val, nullptr, nullptr);
        sgemm<0><<<g2, 256>>>(M, 256, 256, qin, W_off + i * 65536,
                              b_off + i * 256, offb, nullptr, nullptr);
        sgemm<0><<<g1, 256>>>(M, 128, 256, qin, W_attn + i * 32768,
                              b_attn + i * 128, attnb, nullptr, nullptr);
        // deformable sampling
        msda_kernel<<<NQ, 256>>>(offb, attnb, val, sampb);
        // output proj + residual (in-place q)
        sgemm<1><<<g2, 256>>>(M, 256, 256, sampb, W_out + i * 65536,
                              b_out + i * 256, q, ls_a + i * 256, nullptr);
        // pre-FFN norm
        rms_kernel<<<NQ / 8, 256>>>(q, g_nf + i * DIM, nullptr, nbuf, nullptr);
        // FFN: h1 = silu(n@W1^T+b1); h1 *= (n@W3^T+b3); q += ls_f*(h1@W2^T+b2)
        sgemm<2><<<g8, 256>>>(M, DFFN, 256, nbuf, W1 + i * 262144,
                              b1 + i * DFFN, h1, nullptr, nullptr);
        sgemm<3><<<g8, 256>>>(M, DFFN, 256, nbuf, W3 + i * 262144,
                              b3 + i * DFFN, h1, nullptr, h1);
        sgemm<1><<<g2, 256>>>(M, 256, DFFN, h1, W2 + i * 262144,
                              b2 + i * 256, q, ls_f + i * 256, nullptr);
    }

    write_out<<<2048, 256>>>(q, (float*)d_out, out_size);
}

// round 3
// speedup vs baseline: 1.9264x; 1.9264x over previous
#include <cuda_runtime.h>
#include <cuda_bf16.h>
#include <cstdint>
#include <math.h>

#define NTOK   21760
#define BATCH  2
#define NQ     (NTOK*BATCH)
#define DIM    256
#define NLAY   6
#define DFFN   1024
#define QOUT   (NQ*DIM)

typedef __nv_bfloat16 bf16;

__device__ __constant__ int c_LW[4] = {128, 64, 32, 16};
__device__ __constant__ int c_LS[4] = {0, 16384, 20480, 21504};
__constant__ float c_tail[12] = {128.f,128.f,64.f,64.f,32.f,32.f,16.f,16.f,
                                 0.f,16384.f,20480.f,21504.f};

// scratch (device globals; allocation-free), 256B-aligned for vector ld/st
__device__ __align__(256) float g_q   [NQ*DIM];
__device__ __align__(256) float g_posf[NQ*DIM];
__device__ __align__(256) bf16  g_n   [NQ*DIM];
__device__ __align__(256) bf16  g_qin [NQ*DIM];
__device__ __align__(256) bf16  g_val [NQ*DIM];
__device__ __align__(256) float g_off [NQ*DIM];
__device__ __align__(256) float g_attn[NQ*128];
__device__ __align__(256) bf16  g_samp[NQ*DIM];
__device__ __align__(256) bf16  g_h1  [NQ*DFFN];
__device__ __align__(256) bf16  g_woff [NLAY*256*256];
__device__ __align__(256) bf16  g_wattn[NLAY*128*256];
__device__ __align__(256) bf16  g_wval [NLAY*256*256];
__device__ __align__(256) bf16  g_wout [NLAY*256*256];
__device__ __align__(256) bf16  g_w1   [NLAY*DFFN*256];
__device__ __align__(256) bf16  g_w3   [NLAY*DFFN*256];
__device__ __align__(256) bf16  g_w2   [NLAY*256*DFFN];

// ---------------- PTX helpers (compute_80-era; valid on base sm_103) --------
__device__ __forceinline__ uint32_t smem_u32(const void* p) {
    uint32_t a;
    asm("{ .reg .u64 t; cvta.to.shared.u64 t, %1; cvt.u32.u64 %0, t; }"
        : "=r"(a) : "l"(p));
    return a;
}
#define CPASYNC16(saddr, gptr) \
    asm volatile("cp.async.cg.shared.global [%0], [%1], 16;" \
                 :: "r"(saddr), "l"(gptr))
#define CPASYNC_COMMIT() asm volatile("cp.async.commit_group;" ::: "memory")
#define CPASYNC_WAIT(n)  asm volatile("cp.async.wait_group %0;" :: "n"(n) : "memory")
#define LDSM4(d0,d1,d2,d3,addr) \
    asm volatile("ldmatrix.sync.aligned.m8n8.x4.shared.b16 {%0,%1,%2,%3}, [%4];" \
                 : "=r"(d0),"=r"(d1),"=r"(d2),"=r"(d3) : "r"(addr))
#define MMA16816(c, a, b0, b1) \
    asm volatile("mma.sync.aligned.m16n8k16.row.col.f32.bf16.bf16.f32 " \
                 "{%0,%1,%2,%3},{%4,%5,%6,%7},{%8,%9},{%0,%1,%2,%3};" \
                 : "+f"((c)[0]),"+f"((c)[1]),"+f"((c)[2]),"+f"((c)[3]) \
                 : "r"((a)[0]),"r"((a)[1]),"r"((a)[2]),"r"((a)[3]), \
                   "r"(b0),"r"(b1))
#define SWZ128(off) ((off) ^ (((off) >> 3) & 0x70))

__device__ __forceinline__ uint32_t pack_bf2(float a, float b) {
    __nv_bfloat162 h = __floats2bfloat162_rn(a, b);
    return *reinterpret_cast<uint32_t*>(&h);
}

// ================= bf16 tensor-core GEMM =====================================
// C[M,Nc] = A[M,K] @ B[Nc,K]^T + bias     (bf16 in, fp32 accumulate)
// EPI 0: C = v                 (BOUT: bf16 out / fp32 out)
// EPI 1: C[f32] += ls[n] * v   (residual, in-place fp32 q)
// EPI 2: C = silu(v)           (bf16 out)
// EPI 3: C = v * other[m,n]    (bf16 out; other may alias C)
// Tiles: BM=128, BN=64, BK=64. 256 threads = 8 warps (4 M x 2 N), warp 32x32.
template<int EPI, bool BOUT>
__global__ void __launch_bounds__(256)
hgemm(int Nc, int K,
      const bf16* __restrict__ A, const bf16* __restrict__ B,
      const float* __restrict__ bias, void* __restrict__ Cv,
      const float* __restrict__ ls, const bf16* __restrict__ other)
{
    __shared__ uint8_t As[2][16384];   // 128 rows x 128B (64 bf16), SW128
    __shared__ uint8_t Bs[2][8192];    // 64 rows x 128B

    const int tid = threadIdx.x;
    const int lane = tid & 31, wid = tid >> 5;
    const int warp_m = wid >> 1, warp_n = wid & 1;
    const int bn = blockIdx.x, bm = blockIdx.y;

    const uint32_t sA0 = smem_u32(As[0]);
    const uint32_t sB0 = smem_u32(Bs[0]);

    const int NCH = K >> 6;

    // cp.async issue for chunk c into stage s
    auto issue = [&](int c, int s) {
        const bf16* Agp = A + (size_t)(bm * 128) * K + c * 64;
        const bf16* Bgp = B + (size_t)(bn * 64) * K + c * 64;
        uint32_t sa = sA0 + s * 16384, sb = sB0 + s * 8192;
        #pragma unroll
        for (int j = 0; j < 4; j++) {
            int idx = tid + 256 * j;          // 0..1023
            int row = idx >> 3, q = idx & 7;
            CPASYNC16(sa + SWZ128(row * 128 + q * 16),
                      Agp + (size_t)row * K + q * 8);
        }
        #pragma unroll
        for (int j = 0; j < 2; j++) {
            int idx = tid + 256 * j;          // 0..511
            int row = idx >> 3, q = idx & 7;
            CPASYNC16(sb + SWZ128(row * 128 + q * 16),
                      Bgp + (size_t)row * K + q * 8);
        }
        CPASYNC_COMMIT();
    };

    float acc[2][4][4];
    #pragma unroll
    for (int i = 0; i < 2; i++)
        #pragma unroll
        for (int j = 0; j < 4; j++)
            #pragma unroll
            for (int k = 0; k < 4; k++) acc[i][j][k] = 0.f;

    const int mat = lane >> 3, r8 = lane & 7;

    issue(0, 0);
    for (int c = 0; c < NCH; c++) {
        if (c + 1 < NCH) { issue(c + 1, (c + 1) & 1); CPASYNC_WAIT(1); }
        else             { CPASYNC_WAIT(0); }
        __syncthreads();

        uint32_t sa = sA0 + (c & 1) * 16384;
        uint32_t sb = sB0 + (c & 1) * 8192;
        #pragma unroll
        for (int ks = 0; ks < 4; ks++) {
            uint32_t a[2][4], bfr[4][2];
            #pragma unroll
            for (int mt = 0; mt < 2; mt++) {
                int row = warp_m * 32 + mt * 16 + (mat & 1) * 8 + r8;
                int kb  = ks * 32 + (mat >> 1) * 16;
                LDSM4(a[mt][0], a[mt][1], a[mt][2], a[mt][3],
                      sa + SWZ128(row * 128 + kb));
            }
            #pragma unroll
            for (int np = 0; np < 2; np++) {
                int nrow = warp_n * 32 + np * 16 + (mat >> 1) * 8 + r8;
                int kb   = ks * 32 + (mat & 1) * 16;
                uint32_t t0, t1, t2, t3;
                LDSM4(t0, t1, t2, t3, sb + SWZ128(nrow * 128 + kb));
                bfr[np*2+0][0] = t0; bfr[np*2+0][1] = t1;
                bfr[np*2+1][0] = t2; bfr[np*2+1][1] = t3;
            }
            #pragma unroll
            for (int mt = 0; mt < 2; mt++)
                #pragma unroll
                for (int nt = 0; nt < 4; nt++)
                    MMA16816(acc[mt][nt], a[mt], bfr[nt][0], bfr[nt][1]);
        }
        __syncthreads();
    }

    // ---------------- epilogue ----------------
    const int g  = lane >> 2, tg = lane & 3;
    const int rbase = bm * 128 + warp_m * 32;
    const int cbase = bn * 64  + warp_n * 32;

    #pragma unroll
    for (int mt = 0; mt < 2; mt++) {
        #pragma unroll
        for (int nt = 0; nt < 4; nt++) {
            int col = cbase + nt * 8 + tg * 2;
            float2 bs2 = *(const float2*)(bias + col);
            int r0 = rbase + mt * 16 + g;
            float v00 = acc[mt][nt][0] + bs2.x, v01 = acc[mt][nt][1] + bs2.y;
            float v10 = acc[mt][nt][2] + bs2.x, v11 = acc[mt][nt][3] + bs2.y;
            size_t i0 = (size_t)r0 * Nc + col;
            size_t i1 = (size_t)(r0 + 8) * Nc + col;

            if (EPI == 1) {
                float2 ls2 = *(const float2*)(ls + col);
                float* Cf = (float*)Cv;
                float2 q0 = *(float2*)(Cf + i0);
                float2 q1 = *(float2*)(Cf + i1);
                q0.x += ls2.x * v00; q0.y += ls2.y * v01;
                q1.x += ls2.x * v10; q1.y += ls2.y * v11;
                *(float2*)(Cf + i0) = q0;
                *(float2*)(Cf + i1) = q1;
            } else if (!BOUT) {
                float* Cf = (float*)Cv;
                *(float2*)(Cf + i0) = make_float2(v00, v01);
                *(float2*)(Cf + i1) = make_float2(v10, v11);
            } else {
                if (EPI == 2) {
                    v00 = v00 / (1.f + __expf(-v00));
                    v01 = v01 / (1.f + __expf(-v01));
                    v10 = v10 / (1.f + __expf(-v10));
                    v11 = v11 / (1.f + __expf(-v11));
                } else if (EPI == 3) {
                    const bf16* ob = (const bf16*)other;
                    __nv_bfloat162 o0 = *(const __nv_bfloat162*)(ob + i0);
                    __nv_bfloat162 o1 = *(const __nv_bfloat162*)(ob + i1);
                    float2 f0 = __bfloat1622float2(o0);
                    float2 f1 = __bfloat1622float2(o1);
                    v00 *= f0.x; v01 *= f0.y; v10 *= f1.x; v11 *= f1.y;
                }
                bf16* Cb = (bf16*)Cv;
                *(uint32_t*)(Cb + i0) = pack_bf2(v00, v01);
                *(uint32_t*)(Cb + i1) = pack_bf2(v10, v11);
            }
        }
    }
}

__global__ void f2bf(const float* __restrict__ in, bf16* __restrict__ out, int n) {
    for (int i = blockIdx.x * blockDim.x + threadIdx.x; i < n;
         i += gridDim.x * blockDim.x)
        out[i] = __float2bfloat16(in[i]);
}

__global__ void __launch_bounds__(256)
transpose_level(const float* __restrict__ src, float* __restrict__ dst,
                int HW, int start, const float* __restrict__ le)
{
    __shared__ float tile[32][33];
    int b = blockIdx.z, p0 = blockIdx.x * 32, d0 = blockIdx.y * 32;
    int tx = threadIdx.x, ty = threadIdx.y;
    const float* s = src + ((size_t)b * DIM + d0) * HW + p0;
    #pragma unroll
    for (int i = ty; i < 32; i += 8)
        tile[i][tx] = s[(size_t)i * HW + tx];
    __syncthreads();
    #pragma unroll
    for (int i = ty; i < 32; i += 8) {
        float v = tile[tx][i];
        if (le) v += le[d0 + tx];
        dst[((size_t)b * NTOK + start + p0 + i) * DIM + d0 + tx] = v;
    }
}

__global__ void __launch_bounds__(256)
rms_kernel(const float* __restrict__ x, const float* __restrict__ g,
           const float* __restrict__ posf, bf16* __restrict__ out_n,
           bf16* __restrict__ out_qin)
{
    int warp = threadIdx.x >> 5, lane = threadIdx.x & 31;
    int row  = blockIdx.x * 8 + warp;
    const float* xr = x + (size_t)row * DIM;

    float4 v0 = *(const float4*)(xr + lane * 4);
    float4 v1 = *(const float4*)(xr + 128 + lane * 4);
    float s = v0.x*v0.x + v0.y*v0.y + v0.z*v0.z + v0.w*v0.w
            + v1.x*v1.x + v1.y*v1.y + v1.z*v1.z + v1.w*v1.w;
    #pragma unroll
    for (int o = 16; o; o >>= 1) s += __shfl_xor_sync(0xffffffffu, s, o);
    float scale = rsqrtf(s * (1.0f / 256.0f) + 1e-6f);

    float4 ga = *(const float4*)(g + lane * 4);
    float4 gb = *(const float4*)(g + 128 + lane * 4);
    float n0x = v0.x*scale*ga.x, n0y = v0.y*scale*ga.y;
    float n0z = v0.z*scale*ga.z, n0w = v0.w*scale*ga.w;
    float n1x = v1.x*scale*gb.x, n1y = v1.y*scale*gb.y;
    float n1z = v1.z*scale*gb.z, n1w = v1.w*scale*gb.w;

    bf16* nr = out_n + (size_t)row * DIM;
    *(uint2*)(nr + lane * 4)       = make_uint2(pack_bf2(n0x, n0y), pack_bf2(n0z, n0w));
    *(uint2*)(nr + 128 + lane * 4) = make_uint2(pack_bf2(n1x, n1y), pack_bf2(n1z, n1w));

    if (out_qin) {
        const float* pr = posf + (size_t)row * DIM;
        float4 p0 = *(const float4*)(pr + lane * 4);
        float4 p1 = *(const float4*)(pr + 128 + lane * 4);
        bf16* qr = out_qin + (size_t)row * DIM;
        *(uint2*)(qr + lane * 4) =
            make_uint2(pack_bf2(n0x + p0.x, n0y + p0.y), pack_bf2(n0z + p0.z, n0w + p0.w));
        *(uint2*)(qr + 128 + lane * 4) =
            make_uint2(pack_bf2(n1x + p1.x, n1y + p1.y), pack_bf2(n1z + p1.z, n1w + p1.w));
    }
}

__global__ void __launch_bounds__(256)
msda_kernel(const float* __restrict__ off, const float* __restrict__ attnlog,
            const bf16* __restrict__ value, bf16* __restrict__ samp)
{
    int row  = blockIdx.x;
    int h    = threadIdx.x >> 5;
    int lane = threadIdx.x & 31;
    int b = row / NTOK;
    int n = row - b * NTOK;

    int lvl = (n >= 21504) ? 3 : (n >= 20480) ? 2 : (n >= 16384) ? 1 : 0;
    int Wq  = c_LW[lvl];
    int li  = n - c_LS[lvl];
    int iy  = li / Wq, ix = li - iy * Wq;
    float refx = (ix + 0.5f) / (float)Wq;
    float refy = (iy + 0.5f) / (float)Wq;

    const float* al = attnlog + (size_t)row * 128 + h * 16;
    float lg[16];
    float m = -1e30f;
    #pragma unroll
    for (int j = 0; j < 16; j++) { lg[j] = al[j]; m = fmaxf(m, lg[j]); }
    float s = 0.f;
    #pragma unroll
    for (int j = 0; j < 16; j++) { lg[j] = __expf(lg[j] - m); s += lg[j]; }
    float inv = 1.f / s;

    const float* op = off + (size_t)row * 256 + h * 32;
    const bf16*  vb = value + ((size_t)b * NTOK) * 256 + h * 32 + lane;
    float acc = 0.f;

    #pragma unroll
    for (int l = 0; l < 4; l++) {
        int Wl = c_LW[l], st = c_LS[l];
        float fW = (float)Wl;
        #pragma unroll
        for (int p = 0; p < 4; p++) {
            float ox = op[l * 8 + p * 2 + 0];
            float oy = op[l * 8 + p * 2 + 1];
            float xx = (refx + ox / fW) * fW - 0.5f;
            float yy = (refy + oy / fW) * fW - 0.5f;
            float x0f = floorf(xx), y0f = floorf(yy);
            int x0 = (int)x0f, y0 = (int)y0f;
            float fx = xx - x0f, fy = yy - y0f;
            float aw  = lg[l * 4 + p] * inv;
            float w00 = (1.f - fx) * (1.f - fy) * aw;
            float w10 = fx * (1.f - fy) * aw;
            float w01 = (1.f - fx) * fy * aw;
            float w11 = fx * fy * aw;
            bool vx0 = (x0 >= 0)     && (x0 < Wl);
            bool vx1 = (x0 + 1 >= 0) && (x0 + 1 < Wl);
            bool vy0 = (y0 >= 0)     && (y0 < Wl);
            bool vy1 = (y0 + 1 >= 0) && (y0 + 1 < Wl);
            if (vx0 && vy0) acc += w00 * __bfloat162float(vb[(size_t)(st + y0     * Wl + x0    ) * 256]);
            if (vx1 && vy0) acc += w10 * __bfloat162float(vb[(size_t)(st + y0     * Wl + x0 + 1) * 256]);
            if (vx0 && vy1) acc += w01 * __bfloat162float(vb[(size_t)(st + (y0+1) * Wl + x0    ) * 256]);
            if (vx1 && vy1) acc += w11 * __bfloat162float(vb[(size_t)(st + (y0+1) * Wl + x0 + 1) * 256]);
        }
    }
    samp[(size_t)row * 256 + h * 32 + lane] = __float2bfloat16(acc);
}

__global__ void write_out(const float* __restrict__ q, float* __restrict__ out,
                          int out_size)
{
    for (int i = blockIdx.x * blockDim.x + threadIdx.x; i < out_size;
         i += gridDim.x * blockDim.x) {
        float v;
        if (i < QOUT) v = q[i];
        else { int j = i - QOUT; v = (j < 12) ? c_tail[j] : 0.f; }
        out[i] = v;
    }
}

extern "C" void kernel_launch(void* const* d_in, const int* in_sizes, int n_in,
                              void* d_out, int out_size)
{
    (void)n_in;
    const float* src[4];
    const float* pos[4];
    bool interleaved = (in_sizes[1] == in_sizes[0]);
    for (int i = 0; i < 4; i++) {
        if (interleaved) { src[i] = (const float*)d_in[2*i];
                           pos[i] = (const float*)d_in[2*i+1]; }
        else             { src[i] = (const float*)d_in[i];
                           pos[i] = (const float*)d_in[4+i]; }
    }
    const float* level_embed = (const float*)d_in[8];
    const float* W_off  = (const float*)d_in[9];
    const float* b_off  = (const float*)d_in[10];
    const float* W_attn = (const float*)d_in[11];
    const float* b_attn = (const float*)d_in[12];
    const float* W_val  = (const float*)d_in[13];
    const float* b_val  = (const float*)d_in[14];
    const float* W_out  = (const float*)d_in[15];
    const float* b_out  = (const float*)d_in[16];
    const float* g_na   = (const float*)d_in[17];
    const float* g_nf   = (const float*)d_in[18];
    const float* ls_a   = (const float*)d_in[19];
    const float* ls_f   = (const float*)d_in[20];
    const float* W1     = (const float*)d_in[21];
    const float* b1     = (const float*)d_in[22];
    const float* W3     = (const float*)d_in[23];
    const float* b3     = (const float*)d_in[24];
    const float* W2     = (const float*)d_in[25];
    const float* b2     = (const float*)d_in[26];

    float *q, *posf, *offb, *attnb;
    bf16 *nbuf, *qin, *val, *sampb, *h1;
    bf16 *woff, *wattn, *wval, *wout, *w1, *w3, *w2;
    cudaGetSymbolAddress((void**)&q,     g_q);
    cudaGetSymbolAddress((void**)&posf,  g_posf);
    cudaGetSymbolAddress((void**)&nbuf,  g_n);
    cudaGetSymbolAddress((void**)&qin,   g_qin);
    cudaGetSymbolAddress((void**)&val,   g_val);
    cudaGetSymbolAddress((void**)&offb,  g_off);
    cudaGetSymbolAddress((void**)&attnb, g_attn);
    cudaGetSymbolAddress((void**)&sampb, g_samp);
    cudaGetSymbolAddress((void**)&h1,    g_h1);
    cudaGetSymbolAddress((void**)&woff,  g_woff);
    cudaGetSymbolAddress((void**)&wattn, g_wattn);
    cudaGetSymbolAddress((void**)&wval,  g_wval);
    cudaGetSymbolAddress((void**)&wout,  g_wout);
    cudaGetSymbolAddress((void**)&w1,    g_w1);
    cudaGetSymbolAddress((void**)&w3,    g_w3);
    cudaGetSymbolAddress((void**)&w2,    g_w2);

    f2bf<<<1024, 256>>>(W_off,  woff,  NLAY*256*256);
    f2bf<<<1024, 256>>>(W_attn, wattn, NLAY*128*256);
    f2bf<<<1024, 256>>>(W_val,  wval,  NLAY*256*256);
    f2bf<<<1024, 256>>>(W_out,  wout,  NLAY*256*256);
    f2bf<<<1024, 256>>>(W1,     w1,    NLAY*DFFN*256);
    f2bf<<<1024, 256>>>(W3,     w3,    NLAY*DFFN*256);
    f2bf<<<1024, 256>>>(W2,     w2,    NLAY*256*DFFN);

    const int HWs[4]    = {16384, 4096, 1024, 256};
    const int starts[4] = {0, 16384, 20480, 21504};
    for (int l = 0; l < 4; l++) {
        dim3 grid(HWs[l] / 32, DIM / 32, BATCH), blk(32, 8);
        transpose_level<<<grid, blk>>>(src[l], q,    HWs[l], starts[l], nullptr);
        transpose_level<<<grid, blk>>>(pos[l], posf, HWs[l], starts[l],
                                       level_embed + l * DIM);
    }

    const int MT = NQ / 128;                  // 340 row tiles
    dim3 g4(4, MT), g2(2, MT), g16(16, MT);   // N/64 column tiles

    for (int i = 0; i < NLAY; i++) {
        rms_kernel<<<NQ / 8, 256>>>(q, g_na + i * DIM, posf, nbuf, qin);
        hgemm<0,true ><<<g4, 256>>>(256, 256, nbuf, wval + (size_t)i*65536,
                                    b_val + i*256, val, nullptr, nullptr);
        hgemm<0,false><<<g4, 256>>>(256, 256, qin, woff + (size_t)i*65536,
                                    b_off + i*256, offb, nullptr, nullptr);
        hgemm<0,false><<<g2, 256>>>(128, 256, qin, wattn + (size_t)i*32768,
                                    b_attn + i*128, attnb, nullptr, nullptr);
        msda_kernel<<<NQ, 256>>>(offb, attnb, val, sampb);
        hgemm<1,false><<<g4, 256>>>(256, 256, sampb, wout + (size_t)i*65536,
                                    b_out + i*256, q, ls_a + i*256, nullptr);
        rms_kernel<<<NQ / 8, 256>>>(q, g_nf + i * DIM, nullptr, nbuf, nullptr);
        hgemm<2,true ><<<g16, 256>>>(DFFN, 256, nbuf, w1 + (size_t)i*262144,
                                     b1 + i*DFFN, h1, nullptr, nullptr);
        hgemm<3,true ><<<g16, 256>>>(DFFN, 256, nbuf, w3 + (size_t)i*262144,
                                     b3 + i*DFFN, h1, nullptr, h1);
        hgemm<1,false><<<g4, 256>>>(256, DFFN, h1, w2 + (size_t)i*262144,
                                    b2 + i*256, q, ls_f + i*256, nullptr);
    }

    write_out<<<2048, 256>>>(q, (float*)d_out, out_size);
}

// round 4
// speedup vs baseline: 3.7940x; 1.9695x over previous
#include <cuda_runtime.h>
#include <cuda_bf16.h>
#include <cstdint>
#include <math.h>

#define NTOK   21760
#define BATCH  2
#define NQ     (NTOK*BATCH)
#define DIM    256
#define NLAY   6
#define DFFN   1024
#define QOUT   (NQ*DIM)

typedef __nv_bfloat16 bf16;

__device__ __constant__ int c_LW[4] = {128, 64, 32, 16};
__device__ __constant__ int c_LS[4] = {0, 16384, 20480, 21504};
__constant__ float c_tail[12] = {128.f,128.f,64.f,64.f,32.f,32.f,16.f,16.f,
                                 0.f,16384.f,20480.f,21504.f};

// scratch (device globals; allocation-free)
__device__ __align__(256) float g_q   [NQ*DIM];
__device__ __align__(256) float g_posf[NQ*DIM];
__device__ __align__(256) bf16  g_n   [NQ*DIM];
__device__ __align__(256) bf16  g_qin [NQ*DIM];
__device__ __align__(256) bf16  g_val [NQ*DIM];
__device__ __align__(256) float g_oa  [NQ*384];      // off(256) | attn(128)
__device__ __align__(256) bf16  g_samp[NQ*DIM];
__device__ __align__(256) bf16  g_h1  [NQ*DFFN];
__device__ __align__(256) bf16  g_woa  [NLAY*384*256];
__device__ __align__(256) float g_boa  [NLAY*384];
__device__ __align__(256) bf16  g_wval [NLAY*256*256];
__device__ __align__(256) bf16  g_wout [NLAY*256*256];
__device__ __align__(256) bf16  g_w1   [NLAY*DFFN*256];
__device__ __align__(256) bf16  g_w3   [NLAY*DFFN*256];
__device__ __align__(256) bf16  g_w2   [NLAY*256*DFFN];

// ---------------- PTX helpers --------------------------------------------
__device__ __forceinline__ uint32_t smem_u32(const void* p) {
    uint32_t a;
    asm("{ .reg .u64 t; cvta.to.shared.u64 t, %1; cvt.u32.u64 %0, t; }"
        : "=r"(a) : "l"(p));
    return a;
}
#define CPASYNC16(saddr, gptr) \
    asm volatile("cp.async.cg.shared.global [%0], [%1], 16;" \
                 :: "r"(saddr), "l"(gptr))
#define CPASYNC_COMMIT() asm volatile("cp.async.commit_group;" ::: "memory")
#define CPASYNC_WAIT(n)  asm volatile("cp.async.wait_group %0;" :: "n"(n) : "memory")
#define LDSM4(d0,d1,d2,d3,addr) \
    asm volatile("ldmatrix.sync.aligned.m8n8.x4.shared.b16 {%0,%1,%2,%3}, [%4];" \
                 : "=r"(d0),"=r"(d1),"=r"(d2),"=r"(d3) : "r"(addr))
#define MMA16816(c, a, b0, b1) \
    asm volatile("mma.sync.aligned.m16n8k16.row.col.f32.bf16.bf16.f32 " \
                 "{%0,%1,%2,%3},{%4,%5,%6,%7},{%8,%9},{%0,%1,%2,%3};" \
                 : "+f"((c)[0]),"+f"((c)[1]),"+f"((c)[2]),"+f"((c)[3]) \
                 : "r"((a)[0]),"r"((a)[1]),"r"((a)[2]),"r"((a)[3]), \
                   "r"(b0),"r"(b1))
#define SWZ128(off) ((off) ^ (((off) >> 3) & 0x70))

__device__ __forceinline__ uint32_t pack_bf2(float a, float b) {
    __nv_bfloat162 h = __floats2bfloat162_rn(a, b);
    return *reinterpret_cast<uint32_t*>(&h);
}

// ================= bf16 tensor-core GEMM =====================================
// C[M,Nc] = A[M,K] @ B[Nc,K]^T + bias     (bf16 in, fp32 accumulate)
// EPI 0: C = v            EPI 1: C[f32] += ls[n]*v (in-place residual)
// EPI 2: C = silu(v)      EPI 3: C = v * other (alias-safe)
// BM=128, BN=128, BK=64, 3-stage cp.async, 8 warps (2 M x 4 N), warp 64x32.
#define STAGE_BYTES 32768
#define SMEM_TOTAL_GEMM (3*STAGE_BYTES)

template<int EPI, bool BOUT>
__global__ void __launch_bounds__(256, 2)
hgemm(int Nc, int K,
      const bf16* __restrict__ A, const bf16* __restrict__ B,
      const float* __restrict__ bias, void* __restrict__ Cv,
      const float* __restrict__ ls, const bf16* __restrict__ other)
{
    extern __shared__ uint8_t dsm[];
    const uint32_t s0 = smem_u32(dsm);

    const int tid = threadIdx.x;
    const int lane = tid & 31, wid = tid >> 5;
    const int warp_m = wid >> 2, warp_n = wid & 3;   // 2 x 4
    const int bn = blockIdx.x, bm = blockIdx.y;
    const int NCH = K >> 6;

    const bf16* Ag = A + (size_t)(bm * 128) * K;
    const bf16* Bg = B + (size_t)(bn * 128) * K;

    auto issue = [&](int c, int s) {
        uint32_t sa = s0 + s * STAGE_BYTES;
        uint32_t sb = sa + 16384;
        const bf16* Agp = Ag + c * 64;
        const bf16* Bgp = Bg + c * 64;
        #pragma unroll
        for (int j = 0; j < 4; j++) {
            int idx = tid + 256 * j;
            int row = idx >> 3, q = idx & 7;
            CPASYNC16(sa + SWZ128(row * 128 + q * 16),
                      Agp + (size_t)row * K + q * 8);
        }
        #pragma unroll
        for (int j = 0; j < 4; j++) {
            int idx = tid + 256 * j;
            int row = idx >> 3, q = idx & 7;
            CPASYNC16(sb + SWZ128(row * 128 + q * 16),
                      Bgp + (size_t)row * K + q * 8);
        }
        CPASYNC_COMMIT();
    };

    float acc[4][4][4];
    #pragma unroll
    for (int i = 0; i < 4; i++)
        #pragma unroll
        for (int j = 0; j < 4; j++)
            #pragma unroll
            for (int k = 0; k < 4; k++) acc[i][j][k] = 0.f;

    const int mat = lane >> 3, r8 = lane & 7;

    issue(0, 0);
    issue(1, 1);
    int s = 0;
    for (int c = 0; c < NCH; c++) {
        if (c + 1 < NCH) { CPASYNC_WAIT(1); } else { CPASYNC_WAIT(0); }
        __syncthreads();
        if (c + 2 < NCH) issue(c + 2, (s + 2) % 3);

        uint32_t sa = s0 + s * STAGE_BYTES;
        uint32_t sb = sa + 16384;
        #pragma unroll
        for (int ks = 0; ks < 4; ks++) {
            uint32_t a[4][4], bfr[4][2];
            #pragma unroll
            for (int mt = 0; mt < 4; mt++) {
                int row = warp_m * 64 + mt * 16 + (mat & 1) * 8 + r8;
                int kb  = ks * 32 + (mat >> 1) * 16;
                LDSM4(a[mt][0], a[mt][1], a[mt][2], a[mt][3],
                      sa + SWZ128(row * 128 + kb));
            }
            #pragma unroll
            for (int np = 0; np < 2; np++) {
                int nrow = warp_n * 32 + np * 16 + (mat >> 1) * 8 + r8;
                int kb   = ks * 32 + (mat & 1) * 16;
                uint32_t t0, t1, t2, t3;
                LDSM4(t0, t1, t2, t3, sb + SWZ128(nrow * 128 + kb));
                bfr[np*2+0][0] = t0; bfr[np*2+0][1] = t1;
                bfr[np*2+1][0] = t2; bfr[np*2+1][1] = t3;
            }
            #pragma unroll
            for (int mt = 0; mt < 4; mt++)
                #pragma unroll
                for (int nt = 0; nt < 4; nt++)
                    MMA16816(acc[mt][nt], a[mt], bfr[nt][0], bfr[nt][1]);
        }
        s = (s + 1) % 3;
    }

    // ---------------- epilogue ----------------
    const int g  = lane >> 2, tg = lane & 3;
    const int rbase = bm * 128 + warp_m * 64;
    const int cbase = bn * 128 + warp_n * 32;

    #pragma unroll
    for (int mt = 0; mt < 4; mt++) {
        #pragma unroll
        for (int nt = 0; nt < 4; nt++) {
            int col = cbase + nt * 8 + tg * 2;
            float2 bs2 = *(const float2*)(bias + col);
            int r0 = rbase + mt * 16 + g;
            float v00 = acc[mt][nt][0] + bs2.x, v01 = acc[mt][nt][1] + bs2.y;
            float v10 = acc[mt][nt][2] + bs2.x, v11 = acc[mt][nt][3] + bs2.y;
            size_t i0 = (size_t)r0 * Nc + col;
            size_t i1 = (size_t)(r0 + 8) * Nc + col;

            if (EPI == 1) {
                float2 ls2 = *(const float2*)(ls + col);
                float* Cf = (float*)Cv;
                float2 q0 = *(float2*)(Cf + i0);
                float2 q1 = *(float2*)(Cf + i1);
                q0.x += ls2.x * v00; q0.y += ls2.y * v01;
                q1.x += ls2.x * v10; q1.y += ls2.y * v11;
                *(float2*)(Cf + i0) = q0;
                *(float2*)(Cf + i1) = q1;
            } else if (!BOUT) {
                float* Cf = (float*)Cv;
                *(float2*)(Cf + i0) = make_float2(v00, v01);
                *(float2*)(Cf + i1) = make_float2(v10, v11);
            } else {
                if (EPI == 2) {
                    v00 = v00 / (1.f + __expf(-v00));
                    v01 = v01 / (1.f + __expf(-v01));
                    v10 = v10 / (1.f + __expf(-v10));
                    v11 = v11 / (1.f + __expf(-v11));
                } else if (EPI == 3) {
                    const bf16* ob = (const bf16*)other;
                    __nv_bfloat162 o0 = *(const __nv_bfloat162*)(ob + i0);
                    __nv_bfloat162 o1 = *(const __nv_bfloat162*)(ob + i1);
                    float2 f0 = __bfloat1622float2(o0);
                    float2 f1 = __bfloat1622float2(o1);
                    v00 *= f0.x; v01 *= f0.y; v10 *= f1.x; v11 *= f1.y;
                }
                bf16* Cb = (bf16*)Cv;
                *(uint32_t*)(Cb + i0) = pack_bf2(v00, v01);
                *(uint32_t*)(Cb + i1) = pack_bf2(v10, v11);
            }
        }
    }
}

// ---------------- weight prep ----------------
__global__ void f2bf(const float* __restrict__ in, bf16* __restrict__ out, int n) {
    for (int i = blockIdx.x * blockDim.x + threadIdx.x; i < n;
         i += gridDim.x * blockDim.x)
        out[i] = __float2bfloat16(in[i]);
}

__global__ void build_oa(const float* __restrict__ Woff, const float* __restrict__ Wattn,
                         const float* __restrict__ boff, const float* __restrict__ battn,
                         bf16* __restrict__ woa, float* __restrict__ boa)
{
    const int total = NLAY * 384 * 256;
    for (int i = blockIdx.x * blockDim.x + threadIdx.x; i < total;
         i += gridDim.x * blockDim.x) {
        int layer = i / (384 * 256);
        int rem = i - layer * 384 * 256;
        int r = rem >> 8, k = rem & 255;
        float v = (r < 256) ? Woff[layer * 65536 + r * 256 + k]
                            : Wattn[layer * 32768 + (r - 256) * 256 + k];
        woa[i] = __float2bfloat16(v);
    }
    const int tb = NLAY * 384;
    for (int i = blockIdx.x * blockDim.x + threadIdx.x; i < tb;
         i += gridDim.x * blockDim.x) {
        int layer = i / 384, r = i - layer * 384;
        boa[i] = (r < 256) ? boff[layer * 256 + r] : battn[layer * 128 + (r - 256)];
    }
}

__global__ void __launch_bounds__(256)
transpose_level(const float* __restrict__ src, float* __restrict__ dst,
                int HW, int start, const float* __restrict__ le)
{
    __shared__ float tile[32][33];
    int b = blockIdx.z, p0 = blockIdx.x * 32, d0 = blockIdx.y * 32;
    int tx = threadIdx.x, ty = threadIdx.y;
    const float* s = src + ((size_t)b * DIM + d0) * HW + p0;
    #pragma unroll
    for (int i = ty; i < 32; i += 8)
        tile[i][tx] = s[(size_t)i * HW + tx];
    __syncthreads();
    #pragma unroll
    for (int i = ty; i < 32; i += 8) {
        float v = tile[tx][i];
        if (le) v += le[d0 + tx];
        dst[((size_t)b * NTOK + start + p0 + i) * DIM + d0 + tx] = v;
    }
}

__global__ void __launch_bounds__(256)
rms_kernel(const float* __restrict__ x, const float* __restrict__ g,
           const float* __restrict__ posf, bf16* __restrict__ out_n,
           bf16* __restrict__ out_qin)
{
    int warp = threadIdx.x >> 5, lane = threadIdx.x & 31;
    int row  = blockIdx.x * 8 + warp;
    const float* xr = x + (size_t)row * DIM;

    float4 v0 = *(const float4*)(xr + lane * 4);
    float4 v1 = *(const float4*)(xr + 128 + lane * 4);
    float s = v0.x*v0.x + v0.y*v0.y + v0.z*v0.z + v0.w*v0.w
            + v1.x*v1.x + v1.y*v1.y + v1.z*v1.z + v1.w*v1.w;
    #pragma unroll
    for (int o = 16; o; o >>= 1) s += __shfl_xor_sync(0xffffffffu, s, o);
    float scale = rsqrtf(s * (1.0f / 256.0f) + 1e-6f);

    float4 ga = *(const float4*)(g + lane * 4);
    float4 gb = *(const float4*)(g + 128 + lane * 4);
    float n0x = v0.x*scale*ga.x, n0y = v0.y*scale*ga.y;
    float n0z = v0.z*scale*ga.z, n0w = v0.w*scale*ga.w;
    float n1x = v1.x*scale*gb.x, n1y = v1.y*scale*gb.y;
    float n1z = v1.z*scale*gb.z, n1w = v1.w*scale*gb.w;

    bf16* nr = out_n + (size_t)row * DIM;
    *(uint2*)(nr + lane * 4)       = make_uint2(pack_bf2(n0x, n0y), pack_bf2(n0z, n0w));
    *(uint2*)(nr + 128 + lane * 4) = make_uint2(pack_bf2(n1x, n1y), pack_bf2(n1z, n1w));

    if (out_qin) {
        const float* pr = posf + (size_t)row * DIM;
        float4 p0 = *(const float4*)(pr + lane * 4);
        float4 p1 = *(const float4*)(pr + 128 + lane * 4);
        bf16* qr = out_qin + (size_t)row * DIM;
        *(uint2*)(qr + lane * 4) =
            make_uint2(pack_bf2(n0x + p0.x, n0y + p0.y), pack_bf2(n0z + p0.z, n0w + p0.w));
        *(uint2*)(qr + 128 + lane * 4) =
            make_uint2(pack_bf2(n1x + p1.x, n1y + p1.y), pack_bf2(n1z + p1.z, n1w + p1.w));
    }
}

// ---------------- deformable sampling --------------------------------------
// block = token, warp = head; lane = (point_half, channel_pair)
__global__ void __launch_bounds__(256)
msda_kernel(const float* __restrict__ oa, const bf16* __restrict__ value,
            bf16* __restrict__ samp)
{
    int row  = blockIdx.x;
    int h    = threadIdx.x >> 5;
    int lane = threadIdx.x & 31;
    int ch   = lane & 15;        // channel pair (2 bf16)
    int half = lane >> 4;        // point parity
    int b = row / NTOK;
    int n = row - b * NTOK;

    int lvl = (n >= 21504) ? 3 : (n >= 20480) ? 2 : (n >= 16384) ? 1 : 0;
    int Wq  = c_LW[lvl];
    int li  = n - c_LS[lvl];
    int iy  = li / Wq, ix = li - iy * Wq;
    float refx = (ix + 0.5f) / (float)Wq;
    float refy = (iy + 0.5f) / (float)Wq;

    const float* al = oa + (size_t)row * 384 + 256 + h * 16;
    float lg[16];
    float m = -1e30f;
    #pragma unroll
    for (int j = 0; j < 16; j++) { lg[j] = al[j]; m = fmaxf(m, lg[j]); }
    float s = 0.f;
    #pragma unroll
    for (int j = 0; j < 16; j++) { lg[j] = __expf(lg[j] - m); s += lg[j]; }
    float inv = 1.f / s;

    const float* op = oa + (size_t)row * 384 + h * 32;
    const __nv_bfloat162* vb =
        (const __nv_bfloat162*)(value + ((size_t)b * NTOK) * 256 + h * 32) + ch;
    float accx = 0.f, accy = 0.f;

    #pragma unroll
    for (int j = 0; j < 8; j++) {
        int p  = j * 2 + half;        // 0..15
        int l  = p >> 2, pp = p & 3;
        int Wl = c_LW[l], st = c_LS[l];
        float fW = (float)Wl;
        float ox = op[l * 8 + pp * 2 + 0];
        float oy = op[l * 8 + pp * 2 + 1];
        float xx = (refx + ox / fW) * fW - 0.5f;
        float yy = (refy + oy / fW) * fW - 0.5f;
        float x0f = floorf(xx), y0f = floorf(yy);
        int x0 = (int)x0f, y0 = (int)y0f;
        float fx = xx - x0f, fy = yy - y0f;
        float aw  = lg[p] * inv;
        float w00 = (1.f - fx) * (1.f - fy) * aw;
        float w10 = fx * (1.f - fy) * aw;
        float w01 = (1.f - fx) * fy * aw;
        float w11 = fx * fy * aw;
        bool vx0 = (x0 >= 0)     && (x0 < Wl);
        bool vx1 = (x0 + 1 >= 0) && (x0 + 1 < Wl);
        bool vy0 = (y0 >= 0)     && (y0 < Wl);
        bool vy1 = (y0 + 1 >= 0) && (y0 + 1 < Wl);
        if (vx0 && vy0) {
            float2 f = __bfloat1622float2(vb[(size_t)(st + y0 * Wl + x0) * 128]);
            accx += w00 * f.x; accy += w00 * f.y;
        }
        if (vx1 && vy0) {
            float2 f = __bfloat1622float2(vb[(size_t)(st + y0 * Wl + x0 + 1) * 128]);
            accx += w10 * f.x; accy += w10 * f.y;
        }
        if (vx0 && vy1) {
            float2 f = __bfloat1622float2(vb[(size_t)(st + (y0 + 1) * Wl + x0) * 128]);
            accx += w01 * f.x; accy += w01 * f.y;
        }
        if (vx1 && vy1) {
            float2 f = __bfloat1622float2(vb[(size_t)(st + (y0 + 1) * Wl + x0 + 1) * 128]);
            accx += w11 * f.x; accy += w11 * f.y;
        }
    }
    accx += __shfl_xor_sync(0xffffffffu, accx, 16);
    accy += __shfl_xor_sync(0xffffffffu, accy, 16);
    if (half == 0) {
        uint32_t* sp = (uint32_t*)(samp + (size_t)row * 256 + h * 32);
        sp[ch] = pack_bf2(accx, accy);
    }
}

__global__ void write_out(const float* __restrict__ q, float* __restrict__ out,
                          int out_size)
{
    for (int i = blockIdx.x * blockDim.x + threadIdx.x; i < out_size;
         i += gridDim.x * blockDim.x) {
        float v;
        if (i < QOUT) v = q[i];
        else { int j = i - QOUT; v = (j < 12) ? c_tail[j] : 0.f; }
        out[i] = v;
    }
}

// =============================== launcher ====================================
extern "C" void kernel_launch(void* const* d_in, const int* in_sizes, int n_in,
                              void* d_out, int out_size)
{
    (void)n_in;
    const float* src[4];
    const float* pos[4];
    bool interleaved = (in_sizes[1] == in_sizes[0]);
    for (int i = 0; i < 4; i++) {
        if (interleaved) { src[i] = (const float*)d_in[2*i];
                           pos[i] = (const float*)d_in[2*i+1]; }
        else             { src[i] = (const float*)d_in[i];
                           pos[i] = (const float*)d_in[4+i]; }
    }
    const float* level_embed = (const float*)d_in[8];
    const float* W_off  = (const float*)d_in[9];
    const float* b_off  = (const float*)d_in[10];
    const float* W_attn = (const float*)d_in[11];
    const float* b_attn = (const float*)d_in[12];
    const float* W_val  = (const float*)d_in[13];
    const float* b_val  = (const float*)d_in[14];
    const float* W_out  = (const float*)d_in[15];
    const float* b_out  = (const float*)d_in[16];
    const float* g_na   = (const float*)d_in[17];
    const float* g_nf   = (const float*)d_in[18];
    const float* ls_a   = (const float*)d_in[19];
    const float* ls_f   = (const float*)d_in[20];
    const float* W1     = (const float*)d_in[21];
    const float* b1     = (const float*)d_in[22];
    const float* W3     = (const float*)d_in[23];
    const float* b3     = (const float*)d_in[24];
    const float* W2     = (const float*)d_in[25];
    const float* b2     = (const float*)d_in[26];

    float *q, *posf, *oab, *boa;
    bf16 *nbuf, *qin, *val, *sampb, *h1;
    bf16 *woa, *wval, *wout, *w1, *w3, *w2;
    cudaGetSymbolAddress((void**)&q,     g_q);
    cudaGetSymbolAddress((void**)&posf,  g_posf);
    cudaGetSymbolAddress((void**)&nbuf,  g_n);
    cudaGetSymbolAddress((void**)&qin,   g_qin);
    cudaGetSymbolAddress((void**)&val,   g_val);
    cudaGetSymbolAddress((void**)&oab,   g_oa);
    cudaGetSymbolAddress((void**)&sampb, g_samp);
    cudaGetSymbolAddress((void**)&h1,    g_h1);
    cudaGetSymbolAddress((void**)&woa,   g_woa);
    cudaGetSymbolAddress((void**)&boa,   g_boa);
    cudaGetSymbolAddress((void**)&wval,  g_wval);
    cudaGetSymbolAddress((void**)&wout,  g_wout);
    cudaGetSymbolAddress((void**)&w1,    g_w1);
    cudaGetSymbolAddress((void**)&w3,    g_w3);
    cudaGetSymbolAddress((void**)&w2,    g_w2);

    // raise dynamic smem limit for all GEMM instantiations (idempotent)
    cudaFuncSetAttribute((const void*)hgemm<0,true >, cudaFuncAttributeMaxDynamicSharedMemorySize, SMEM_TOTAL_GEMM);
    cudaFuncSetAttribute((const void*)hgemm<0,false>, cudaFuncAttributeMaxDynamicSharedMemorySize, SMEM_TOTAL_GEMM);
    cudaFuncSetAttribute((const void*)hgemm<1,false>, cudaFuncAttributeMaxDynamicSharedMemorySize, SMEM_TOTAL_GEMM);
    cudaFuncSetAttribute((const void*)hgemm<2,true >, cudaFuncAttributeMaxDynamicSharedMemorySize, SMEM_TOTAL_GEMM);
    cudaFuncSetAttribute((const void*)hgemm<3,true >, cudaFuncAttributeMaxDynamicSharedMemorySize, SMEM_TOTAL_GEMM);

    f2bf<<<1024, 256>>>(W_val,  wval,  NLAY*256*256);
    f2bf<<<1024, 256>>>(W_out,  wout,  NLAY*256*256);
    f2bf<<<1024, 256>>>(W1,     w1,    NLAY*DFFN*256);
    f2bf<<<1024, 256>>>(W3,     w3,    NLAY*DFFN*256);
    f2bf<<<1024, 256>>>(W2,     w2,    NLAY*256*DFFN);
    build_oa<<<1024, 256>>>(W_off, W_attn, b_off, b_attn, woa, boa);

    const int HWs[4]    = {16384, 4096, 1024, 256};
    const int starts[4] = {0, 16384, 20480, 21504};
    for (int l = 0; l < 4; l++) {
        dim3 grid(HWs[l] / 32, DIM / 32, BATCH), blk(32, 8);
        transpose_level<<<grid, blk>>>(src[l], q,    HWs[l], starts[l], nullptr);
        transpose_level<<<grid, blk>>>(pos[l], posf, HWs[l], starts[l],
                                       level_embed + l * DIM);
    }

    const int MT = NQ / 128;                  // 340 row tiles
    dim3 g2(2, MT), g3(3, MT), g8(8, MT);
    const int SB = SMEM_TOTAL_GEMM;

    for (int i = 0; i < NLAY; i++) {
        rms_kernel<<<NQ / 8, 256>>>(q, g_na + i * DIM, posf, nbuf, qin);
        hgemm<0,true ><<<g2, 256, SB>>>(256, 256, nbuf, wval + (size_t)i*65536,
                                        b_val + i*256, val, nullptr, nullptr);
        hgemm<0,false><<<g3, 256, SB>>>(384, 256, qin, woa + (size_t)i*98304,
                                        boa + i*384, oab, nullptr, nullptr);
        msda_kernel<<<NQ, 256>>>(oab, val, sampb);
        hgemm<1,false><<<g2, 256, SB>>>(256, 256, sampb, wout + (size_t)i*65536,
                                        b_out + i*256, q, ls_a + i*256, nullptr);
        rms_kernel<<<NQ / 8, 256>>>(q, g_nf + i * DIM, nullptr, nbuf, nullptr);
        hgemm<2,true ><<<g8, 256, SB>>>(DFFN, 256, nbuf, w1 + (size_t)i*262144,
                                        b1 + i*DFFN, h1, nullptr, nullptr);
        hgemm<3,true ><<<g8, 256, SB>>>(DFFN, 256, nbuf, w3 + (size_t)i*262144,
                                        b3 + i*DFFN, h1, nullptr, h1);
        hgemm<1,false><<<g2, 256, SB>>>(256, DFFN, h1, w2 + (size_t)i*262144,
                                        b2 + i*256, q, ls_f + i*256, nullptr);
    }

    write_out<<<2048, 256>>>(q, (float*)d_out, out_size);
}

// round 5
// speedup vs baseline: 3.8642x; 1.0185x over previous
#include <cuda_runtime.h>
#include <cuda_bf16.h>
#include <cstdint>
#include <math.h>

#define NTOK   21760
#define BATCH  2
#define NQ     (NTOK*BATCH)
#define DIM    256
#define NLAY   6
#define DFFN   1024
#define QOUT   (NQ*DIM)

typedef __nv_bfloat16 bf16;

__device__ __constant__ int c_LW[4] = {128, 64, 32, 16};
__device__ __constant__ int c_LS[4] = {0, 16384, 20480, 21504};
__constant__ float c_tail[12] = {128.f,128.f,64.f,64.f,32.f,32.f,16.f,16.f,
                                 0.f,16384.f,20480.f,21504.f};

// scratch (device globals; allocation-free)
__device__ __align__(256) float g_q   [NQ*DIM];
__device__ __align__(256) float g_posf[NQ*DIM];
__device__ __align__(256) bf16  g_n   [NQ*DIM];
__device__ __align__(256) bf16  g_qin [NQ*DIM];
__device__ __align__(256) bf16  g_val [NQ*DIM];
__device__ __align__(256) bf16  g_oa  [NQ*384];      // off(256) | attn(128), bf16
__device__ __align__(256) bf16  g_samp[NQ*DIM];
__device__ __align__(256) bf16  g_h1  [NQ*DFFN];
__device__ __align__(256) bf16  g_woa  [NLAY*384*256];
__device__ __align__(256) float g_boa  [NLAY*384];
__device__ __align__(256) bf16  g_wval [NLAY*256*256];
__device__ __align__(256) bf16  g_wout [NLAY*256*256];
__device__ __align__(256) bf16  g_wg   [NLAY*2048*256];  // interleaved W1/W3
__device__ __align__(256) float g_bg   [NLAY*2048];
__device__ __align__(256) bf16  g_w2   [NLAY*256*DFFN];

// ---------------- PTX helpers --------------------------------------------
__device__ __forceinline__ uint32_t smem_u32(const void* p) {
    uint32_t a;
    asm("{ .reg .u64 t; cvta.to.shared.u64 t, %1; cvt.u32.u64 %0, t; }"
        : "=r"(a) : "l"(p));
    return a;
}
#define CPASYNC16(saddr, gptr) \
    asm volatile("cp.async.cg.shared.global [%0], [%1], 16;" \
                 :: "r"(saddr), "l"(gptr))
#define CPASYNC_COMMIT() asm volatile("cp.async.commit_group;" ::: "memory")
#define CPASYNC_WAIT(n)  asm volatile("cp.async.wait_group %0;" :: "n"(n) : "memory")
#define LDSM4(d0,d1,d2,d3,addr) \
    asm volatile("ldmatrix.sync.aligned.m8n8.x4.shared.b16 {%0,%1,%2,%3}, [%4];" \
                 : "=r"(d0),"=r"(d1),"=r"(d2),"=r"(d3) : "r"(addr))
#define MMA16816(c, a, b0, b1) \
    asm volatile("mma.sync.aligned.m16n8k16.row.col.f32.bf16.bf16.f32 " \
                 "{%0,%1,%2,%3},{%4,%5,%6,%7},{%8,%9},{%0,%1,%2,%3};" \
                 : "+f"((c)[0]),"+f"((c)[1]),"+f"((c)[2]),"+f"((c)[3]) \
                 : "r"((a)[0]),"r"((a)[1]),"r"((a)[2]),"r"((a)[3]), \
                   "r"(b0),"r"(b1))
#define SWZ128(off) ((off) ^ (((off) >> 3) & 0x70))

__device__ __forceinline__ uint32_t pack_bf2(float a, float b) {
    __nv_bfloat162 h = __floats2bfloat162_rn(a, b);
    return *reinterpret_cast<uint32_t*>(&h);
}

// ================= bf16 tensor-core GEMM =====================================
// C[M,Nc] = A[M,K] @ B[Nc,K]^T + bias     (bf16 in, fp32 accumulate)
// EPI 0: C = v                      (BOUT: bf16 / fp32 out)
// EPI 1: C[f32] += ls[n]*v          (in-place residual)
// EPI 4: GLU: h1[m, n/2] = silu(v_even) * v_odd   (bf16 out, width Nc/2)
// BM=128, BN=128, BK=64, 3-stage cp.async, 8 warps (2 M x 4 N), warp 64x32.
#define STAGE_BYTES 32768
#define SMEM_TOTAL_GEMM (3*STAGE_BYTES)

template<int EPI, bool BOUT>
__global__ void __launch_bounds__(256, 2)
hgemm(int Nc, int K,
      const bf16* __restrict__ A, const bf16* __restrict__ B,
      const float* __restrict__ bias, void* __restrict__ Cv,
      const float* __restrict__ ls)
{
    extern __shared__ uint8_t dsm[];
    const uint32_t s0 = smem_u32(dsm);

    const int tid = threadIdx.x;
    const int lane = tid & 31, wid = tid >> 5;
    const int warp_m = wid >> 2, warp_n = wid & 3;   // 2 x 4
    const int bn = blockIdx.x, bm = blockIdx.y;
    const int NCH = K >> 6;

    const bf16* Ag = A + (size_t)(bm * 128) * K;
    const bf16* Bg = B + (size_t)(bn * 128) * K;

    auto issue = [&](int c, int s) {
        uint32_t sa = s0 + s * STAGE_BYTES;
        uint32_t sb = sa + 16384;
        const bf16* Agp = Ag + c * 64;
        const bf16* Bgp = Bg + c * 64;
        #pragma unroll
        for (int j = 0; j < 4; j++) {
            int idx = tid + 256 * j;
            int row = idx >> 3, q = idx & 7;
            CPASYNC16(sa + SWZ128(row * 128 + q * 16),
                      Agp + (size_t)row * K + q * 8);
        }
        #pragma unroll
        for (int j = 0; j < 4; j++) {
            int idx = tid + 256 * j;
            int row = idx >> 3, q = idx & 7;
            CPASYNC16(sb + SWZ128(row * 128 + q * 16),
                      Bgp + (size_t)row * K + q * 8);
        }
        CPASYNC_COMMIT();
    };

    float acc[4][4][4];
    #pragma unroll
    for (int i = 0; i < 4; i++)
        #pragma unroll
        for (int j = 0; j < 4; j++)
            #pragma unroll
            for (int k = 0; k < 4; k++) acc[i][j][k] = 0.f;

    const int mat = lane >> 3, r8 = lane & 7;

    issue(0, 0);
    issue(1, 1);
    int s = 0;
    for (int c = 0; c < NCH; c++) {
        if (c + 1 < NCH) { CPASYNC_WAIT(1); } else { CPASYNC_WAIT(0); }
        __syncthreads();
        if (c + 2 < NCH) issue(c + 2, (s + 2) % 3);

        uint32_t sa = s0 + s * STAGE_BYTES;
        uint32_t sb = sa + 16384;
        #pragma unroll
        for (int ks = 0; ks < 4; ks++) {
            uint32_t a[4][4], bfr[4][2];
            #pragma unroll
            for (int mt = 0; mt < 4; mt++) {
                int row = warp_m * 64 + mt * 16 + (mat & 1) * 8 + r8;
                int kb  = ks * 32 + (mat >> 1) * 16;
                LDSM4(a[mt][0], a[mt][1], a[mt][2], a[mt][3],
                      sa + SWZ128(row * 128 + kb));
            }
            #pragma unroll
            for (int np = 0; np < 2; np++) {
                int nrow = warp_n * 32 + np * 16 + (mat >> 1) * 8 + r8;
                int kb   = ks * 32 + (mat & 1) * 16;
                uint32_t t0, t1, t2, t3;
                LDSM4(t0, t1, t2, t3, sb + SWZ128(nrow * 128 + kb));
                bfr[np*2+0][0] = t0; bfr[np*2+0][1] = t1;
                bfr[np*2+1][0] = t2; bfr[np*2+1][1] = t3;
            }
            #pragma unroll
            for (int mt = 0; mt < 4; mt++)
                #pragma unroll
                for (int nt = 0; nt < 4; nt++)
                    MMA16816(acc[mt][nt], a[mt], bfr[nt][0], bfr[nt][1]);
        }
        s = (s + 1) % 3;
    }

    // ---------------- epilogue ----------------
    const int g  = lane >> 2, tg = lane & 3;
    const int rbase = bm * 128 + warp_m * 64;
    const int cbase = bn * 128 + warp_n * 32;

    #pragma unroll
    for (int mt = 0; mt < 4; mt++) {
        #pragma unroll
        for (int nt = 0; nt < 4; nt++) {
            int col = cbase + nt * 8 + tg * 2;
            float2 bs2 = *(const float2*)(bias + col);
            int r0 = rbase + mt * 16 + g;
            float v00 = acc[mt][nt][0] + bs2.x, v01 = acc[mt][nt][1] + bs2.y;
            float v10 = acc[mt][nt][2] + bs2.x, v11 = acc[mt][nt][3] + bs2.y;

            if (EPI == 4) {
                // col even = v1, col+1 = v3 ; output column j = col/2, width Nc/2
                int j = col >> 1;
                int ncout = Nc >> 1;
                float g0 = (v00 / (1.f + __expf(-v00))) * v01;
                float g1 = (v10 / (1.f + __expf(-v10))) * v11;
                bf16* Cb = (bf16*)Cv;
                Cb[(size_t)r0 * ncout + j]       = __float2bfloat16(g0);
                Cb[(size_t)(r0 + 8) * ncout + j] = __float2bfloat16(g1);
            } else {
                size_t i0 = (size_t)r0 * Nc + col;
                size_t i1 = (size_t)(r0 + 8) * Nc + col;
                if (EPI == 1) {
                    float2 ls2 = *(const float2*)(ls + col);
                    float* Cf = (float*)Cv;
                    float2 q0 = *(float2*)(Cf + i0);
                    float2 q1 = *(float2*)(Cf + i1);
                    q0.x += ls2.x * v00; q0.y += ls2.y * v01;
                    q1.x += ls2.x * v10; q1.y += ls2.y * v11;
                    *(float2*)(Cf + i0) = q0;
                    *(float2*)(Cf + i1) = q1;
                } else if (!BOUT) {
                    float* Cf = (float*)Cv;
                    *(float2*)(Cf + i0) = make_float2(v00, v01);
                    *(float2*)(Cf + i1) = make_float2(v10, v11);
                } else {
                    bf16* Cb = (bf16*)Cv;
                    *(uint32_t*)(Cb + i0) = pack_bf2(v00, v01);
                    *(uint32_t*)(Cb + i1) = pack_bf2(v10, v11);
                }
            }
        }
    }
}

// ---------------- weight prep ----------------
__global__ void f2bf(const float* __restrict__ in, bf16* __restrict__ out, int n) {
    for (int i = blockIdx.x * blockDim.x + threadIdx.x; i < n;
         i += gridDim.x * blockDim.x)
        out[i] = __float2bfloat16(in[i]);
}

__global__ void build_oa(const float* __restrict__ Woff, const float* __restrict__ Wattn,
                         const float* __restrict__ boff, const float* __restrict__ battn,
                         bf16* __restrict__ woa, float* __restrict__ boa)
{
    const int total = NLAY * 384 * 256;
    for (int i = blockIdx.x * blockDim.x + threadIdx.x; i < total;
         i += gridDim.x * blockDim.x) {
        int layer = i / (384 * 256);
        int rem = i - layer * 384 * 256;
        int r = rem >> 8, k = rem & 255;
        float v = (r < 256) ? Woff[layer * 65536 + r * 256 + k]
                            : Wattn[layer * 32768 + (r - 256) * 256 + k];
        woa[i] = __float2bfloat16(v);
    }
    const int tb = NLAY * 384;
    for (int i = blockIdx.x * blockDim.x + threadIdx.x; i < tb;
         i += gridDim.x * blockDim.x) {
        int layer = i / 384, r = i - layer * 384;
        boa[i] = (r < 256) ? boff[layer * 256 + r] : battn[layer * 128 + (r - 256)];
    }
}

// interleave W1/W3 -> Wg[2048,256] rows (2j -> W1_j, 2j+1 -> W3_j); bias likewise
__global__ void build_glu(const float* __restrict__ W1, const float* __restrict__ W3,
                          const float* __restrict__ b1, const float* __restrict__ b3,
                          bf16* __restrict__ wg, float* __restrict__ bg)
{
    const int total = NLAY * 2048 * 256;
    for (int i = blockIdx.x * blockDim.x + threadIdx.x; i < total;
         i += gridDim.x * blockDim.x) {
        int layer = i / (2048 * 256);
        int rem = i - layer * 2048 * 256;
        int r = rem >> 8, k = rem & 255;
        int j = r >> 1, sel = r & 1;
        const float* Wsrc = sel ? W3 : W1;
        wg[i] = __float2bfloat16(Wsrc[(size_t)layer * DFFN * 256 + j * 256 + k]);
    }
    const int tb = NLAY * 2048;
    for (int i = blockIdx.x * blockDim.x + threadIdx.x; i < tb;
         i += gridDim.x * blockDim.x) {
        int layer = i / 2048, r = i - layer * 2048;
        int j = r >> 1, sel = r & 1;
        bg[i] = sel ? b3[layer * DFFN + j] : b1[layer * DFFN + j];
    }
}

__global__ void __launch_bounds__(256)
transpose_level(const float* __restrict__ src, float* __restrict__ dst,
                int HW, int start, const float* __restrict__ le)
{
    __shared__ float tile[32][33];
    int b = blockIdx.z, p0 = blockIdx.x * 32, d0 = blockIdx.y * 32;
    int tx = threadIdx.x, ty = threadIdx.y;
    const float* s = src + ((size_t)b * DIM + d0) * HW + p0;
    #pragma unroll
    for (int i = ty; i < 32; i += 8)
        tile[i][tx] = s[(size_t)i * HW + tx];
    __syncthreads();
    #pragma unroll
    for (int i = ty; i < 32; i += 8) {
        float v = tile[tx][i];
        if (le) v += le[d0 + tx];
        dst[((size_t)b * NTOK + start + p0 + i) * DIM + d0 + tx] = v;
    }
}

__global__ void __launch_bounds__(256)
rms_kernel(const float* __restrict__ x, const float* __restrict__ g,
           const float* __restrict__ posf, bf16* __restrict__ out_n,
           bf16* __restrict__ out_qin)
{
    int warp = threadIdx.x >> 5, lane = threadIdx.x & 31;
    int row  = blockIdx.x * 8 + warp;
    const float* xr = x + (size_t)row * DIM;

    float4 v0 = *(const float4*)(xr + lane * 4);
    float4 v1 = *(const float4*)(xr + 128 + lane * 4);
    float s = v0.x*v0.x + v0.y*v0.y + v0.z*v0.z + v0.w*v0.w
            + v1.x*v1.x + v1.y*v1.y + v1.z*v1.z + v1.w*v1.w;
    #pragma unroll
    for (int o = 16; o; o >>= 1) s += __shfl_xor_sync(0xffffffffu, s, o);
    float scale = rsqrtf(s * (1.0f / 256.0f) + 1e-6f);

    float4 ga = *(const float4*)(g + lane * 4);
    float4 gb = *(const float4*)(g + 128 + lane * 4);
    float n0x = v0.x*scale*ga.x, n0y = v0.y*scale*ga.y;
    float n0z = v0.z*scale*ga.z, n0w = v0.w*scale*ga.w;
    float n1x = v1.x*scale*gb.x, n1y = v1.y*scale*gb.y;
    float n1z = v1.z*scale*gb.z, n1w = v1.w*scale*gb.w;

    bf16* nr = out_n + (size_t)row * DIM;
    *(uint2*)(nr + lane * 4)       = make_uint2(pack_bf2(n0x, n0y), pack_bf2(n0z, n0w));
    *(uint2*)(nr + 128 + lane * 4) = make_uint2(pack_bf2(n1x, n1y), pack_bf2(n1z, n1w));

    if (out_qin) {
        const float* pr = posf + (size_t)row * DIM;
        float4 p0 = *(const float4*)(pr + lane * 4);
        float4 p1 = *(const float4*)(pr + 128 + lane * 4);
        bf16* qr = out_qin + (size_t)row * DIM;
        *(uint2*)(qr + lane * 4) =
            make_uint2(pack_bf2(n0x + p0.x, n0y + p0.y), pack_bf2(n0z + p0.z, n0w + p0.w));
        *(uint2*)(qr + 128 + lane * 4) =
            make_uint2(pack_bf2(n1x + p1.x, n1y + p1.y), pack_bf2(n1z + p1.z, n1w + p1.w));
    }
}

// ---------------- deformable sampling (bf16 oa) -----------------------------
__global__ void __launch_bounds__(256)
msda_kernel(const bf16* __restrict__ oa, const bf16* __restrict__ value,
            bf16* __restrict__ samp)
{
    int row  = blockIdx.x;
    int h    = threadIdx.x >> 5;
    int lane = threadIdx.x & 31;
    int ch   = lane & 15;        // channel pair (2 bf16)
    int half = lane >> 4;        // point parity
    int b = row / NTOK;
    int n = row - b * NTOK;

    int lvl = (n >= 21504) ? 3 : (n >= 20480) ? 2 : (n >= 16384) ? 1 : 0;
    int Wq  = c_LW[lvl];
    int li  = n - c_LS[lvl];
    int iy  = li / Wq, ix = li - iy * Wq;
    float refx = (ix + 0.5f) / (float)Wq;
    float refy = (iy + 0.5f) / (float)Wq;

    const bf16* al = oa + (size_t)row * 384 + 256 + h * 16;
    float lg[16];
    float m = -1e30f;
    #pragma unroll
    for (int j = 0; j < 8; j++) {
        float2 f = __bfloat1622float2(((const __nv_bfloat162*)al)[j]);
        lg[2*j] = f.x; lg[2*j+1] = f.y;
        m = fmaxf(m, fmaxf(f.x, f.y));
    }
    float s = 0.f;
    #pragma unroll
    for (int j = 0; j < 16; j++) { lg[j] = __expf(lg[j] - m); s += lg[j]; }
    float inv = 1.f / s;

    const __nv_bfloat162* op = (const __nv_bfloat162*)(oa + (size_t)row * 384 + h * 32);
    const __nv_bfloat162* vb =
        (const __nv_bfloat162*)(value + ((size_t)b * NTOK) * 256 + h * 32) + ch;
    float accx = 0.f, accy = 0.f;

    #pragma unroll
    for (int j = 0; j < 8; j++) {
        int p  = j * 2 + half;        // 0..15
        int l  = p >> 2;
        int Wl = c_LW[l], st = c_LS[l];
        float fW = (float)Wl;
        float2 o2 = __bfloat1622float2(op[p]);
        float xx = (refx + o2.x / fW) * fW - 0.5f;
        float yy = (refy + o2.y / fW) * fW - 0.5f;
        float x0f = floorf(xx), y0f = floorf(yy);
        int x0 = (int)x0f, y0 = (int)y0f;
        float fx = xx - x0f, fy = yy - y0f;
        float aw  = lg[p] * inv;
        float w00 = (1.f - fx) * (1.f - fy) * aw;
        float w10 = fx * (1.f - fy) * aw;
        float w01 = (1.f - fx) * fy * aw;
        float w11 = fx * fy * aw;
        bool vx0 = (x0 >= 0)     && (x0 < Wl);
        bool vx1 = (x0 + 1 >= 0) && (x0 + 1 < Wl);
        bool vy0 = (y0 >= 0)     && (y0 < Wl);
        bool vy1 = (y0 + 1 >= 0) && (y0 + 1 < Wl);
        if (vx0 && vy0) {
            float2 f = __bfloat1622float2(vb[(size_t)(st + y0 * Wl + x0) * 128]);
            accx += w00 * f.x; accy += w00 * f.y;
        }
        if (vx1 && vy0) {
            float2 f = __bfloat1622float2(vb[(size_t)(st + y0 * Wl + x0 + 1) * 128]);
            accx += w10 * f.x; accy += w10 * f.y;
        }
        if (vx0 && vy1) {
            float2 f = __bfloat1622float2(vb[(size_t)(st + (y0 + 1) * Wl + x0) * 128]);
            accx += w01 * f.x; accy += w01 * f.y;
        }
        if (vx1 && vy1) {
            float2 f = __bfloat1622float2(vb[(size_t)(st + (y0 + 1) * Wl + x0 + 1) * 128]);
            accx += w11 * f.x; accy += w11 * f.y;
        }
    }
    accx += __shfl_xor_sync(0xffffffffu, accx, 16);
    accy += __shfl_xor_sync(0xffffffffu, accy, 16);
    if (half == 0) {
        uint32_t* sp = (uint32_t*)(samp + (size_t)row * 256 + h * 32);
        sp[ch] = pack_bf2(accx, accy);
    }
}

__global__ void write_out(const float* __restrict__ q, float* __restrict__ out,
                          int out_size)
{
    for (int i = blockIdx.x * blockDim.x + threadIdx.x; i < out_size;
         i += gridDim.x * blockDim.x) {
        float v;
        if (i < QOUT) v = q[i];
        else { int j = i - QOUT; v = (j < 12) ? c_tail[j] : 0.f; }
        out[i] = v;
    }
}

// =============================== launcher ====================================
extern "C" void kernel_launch(void* const* d_in, const int* in_sizes, int n_in,
                              void* d_out, int out_size)
{
    (void)n_in;
    const float* src[4];
    const float* pos[4];
    bool interleaved = (in_sizes[1] == in_sizes[0]);
    for (int i = 0; i < 4; i++) {
        if (interleaved) { src[i] = (const float*)d_in[2*i];
                           pos[i] = (const float*)d_in[2*i+1]; }
        else             { src[i] = (const float*)d_in[i];
                           pos[i] = (const float*)d_in[4+i]; }
    }
    const float* level_embed = (const float*)d_in[8];
    const float* W_off  = (const float*)d_in[9];
    const float* b_off  = (const float*)d_in[10];
    const float* W_attn = (const float*)d_in[11];
    const float* b_attn = (const float*)d_in[12];
    const float* W_val  = (const float*)d_in[13];
    const float* b_val  = (const float*)d_in[14];
    const float* W_out  = (const float*)d_in[15];
    const float* b_out  = (const float*)d_in[16];
    const float* g_na   = (const float*)d_in[17];
    const float* g_nf   = (const float*)d_in[18];
    const float* ls_a   = (const float*)d_in[19];
    const float* ls_f   = (const float*)d_in[20];
    const float* W1     = (const float*)d_in[21];
    const float* b1     = (const float*)d_in[22];
    const float* W3     = (const float*)d_in[23];
    const float* b3     = (const float*)d_in[24];
    const float* W2     = (const float*)d_in[25];
    const float* b2     = (const float*)d_in[26];

    float *q, *posf, *boa, *bg;
    bf16 *nbuf, *qin, *val, *oab, *sampb, *h1;
    bf16 *woa, *wval, *wout, *wg, *w2;
    cudaGetSymbolAddress((void**)&q,     g_q);
    cudaGetSymbolAddress((void**)&posf,  g_posf);
    cudaGetSymbolAddress((void**)&nbuf,  g_n);
    cudaGetSymbolAddress((void**)&qin,   g_qin);
    cudaGetSymbolAddress((void**)&val,   g_val);
    cudaGetSymbolAddress((void**)&oab,   g_oa);
    cudaGetSymbolAddress((void**)&sampb, g_samp);
    cudaGetSymbolAddress((void**)&h1,    g_h1);
    cudaGetSymbolAddress((void**)&woa,   g_woa);
    cudaGetSymbolAddress((void**)&boa,   g_boa);
    cudaGetSymbolAddress((void**)&wval,  g_wval);
    cudaGetSymbolAddress((void**)&wout,  g_wout);
    cudaGetSymbolAddress((void**)&wg,    g_wg);
    cudaGetSymbolAddress((void**)&bg,    g_bg);
    cudaGetSymbolAddress((void**)&w2,    g_w2);

    cudaFuncSetAttribute((const void*)hgemm<0,true >, cudaFuncAttributeMaxDynamicSharedMemorySize, SMEM_TOTAL_GEMM);
    cudaFuncSetAttribute((const void*)hgemm<1,false>, cudaFuncAttributeMaxDynamicSharedMemorySize, SMEM_TOTAL_GEMM);
    cudaFuncSetAttribute((const void*)hgemm<4,true >, cudaFuncAttributeMaxDynamicSharedMemorySize, SMEM_TOTAL_GEMM);

    f2bf<<<1024, 256>>>(W_val,  wval,  NLAY*256*256);
    f2bf<<<1024, 256>>>(W_out,  wout,  NLAY*256*256);
    f2bf<<<1024, 256>>>(W2,     w2,    NLAY*256*DFFN);
    build_oa<<<1024, 256>>>(W_off, W_attn, b_off, b_attn, woa, boa);
    build_glu<<<2048, 256>>>(W1, W3, b1, b3, wg, bg);

    const int HWs[4]    = {16384, 4096, 1024, 256};
    const int starts[4] = {0, 16384, 20480, 21504};
    for (int l = 0; l < 4; l++) {
        dim3 grid(HWs[l] / 32, DIM / 32, BATCH), blk(32, 8);
        transpose_level<<<grid, blk>>>(src[l], q,    HWs[l], starts[l], nullptr);
        transpose_level<<<grid, blk>>>(pos[l], posf, HWs[l], starts[l],
                                       level_embed + l * DIM);
    }

    const int MT = NQ / 128;                  // 340 row tiles
    dim3 g2(2, MT), g3(3, MT), g16(16, MT);
    const int SB = SMEM_TOTAL_GEMM;

    for (int i = 0; i < NLAY; i++) {
        rms_kernel<<<NQ / 8, 256>>>(q, g_na + i * DIM, posf, nbuf, qin);
        hgemm<0,true ><<<g2, 256, SB>>>(256, 256, nbuf, wval + (size_t)i*65536,
                                        b_val + i*256, val, nullptr);
        hgemm<0,true ><<<g3, 256, SB>>>(384, 256, qin, woa + (size_t)i*98304,
                                        boa + i*384, oab, nullptr);
        msda_kernel<<<NQ, 256>>>(oab, val, sampb);
        hgemm<1,false><<<g2, 256, SB>>>(256, 256, sampb, wout + (size_t)i*65536,
                                        b_out + i*256, q, ls_a + i*256);
        rms_kernel<<<NQ / 8, 256>>>(q, g_nf + i * DIM, nullptr, nbuf, nullptr);
        hgemm<4,true ><<<g16, 256, SB>>>(2048, 256, nbuf, wg + (size_t)i*524288,
                                         bg + i*2048, h1, nullptr);
        hgemm<1,false><<<g2, 256, SB>>>(256, DFFN, h1, w2 + (size_t)i*262144,
                                        b2 + i*256, q, ls_f + i*256);
    }

    write_out<<<2048, 256>>>(q, (float*)d_out, out_size);
}

// round 6
// speedup vs baseline: 3.8736x; 1.0024x over previous
#include <cuda_runtime.h>
#include <cuda_bf16.h>
#include <cstdint>
#include <math.h>

#define NTOK   21760
#define BATCH  2
#define NQ     (NTOK*BATCH)
#define DIM    256
#define NLAY   6
#define DFFN   1024
#define QOUT   (NQ*DIM)

typedef __nv_bfloat16 bf16;

__device__ __constant__ int c_LW[4] = {128, 64, 32, 16};
__device__ __constant__ int c_LS[4] = {0, 16384, 20480, 21504};
__constant__ float c_tail[12] = {128.f,128.f,64.f,64.f,32.f,32.f,16.f,16.f,
                                 0.f,16384.f,20480.f,21504.f};

// scratch (device globals; allocation-free)
__device__ __align__(256) float g_q   [NQ*DIM];
__device__ __align__(256) float g_posf[NQ*DIM];
__device__ __align__(256) bf16  g_n   [NQ*DIM];
__device__ __align__(256) bf16  g_qin [NQ*DIM];
__device__ __align__(256) bf16  g_val [NQ*DIM];
__device__ __align__(256) bf16  g_oa  [NQ*384];      // off(256) | attn(128)
__device__ __align__(256) bf16  g_samp[NQ*DIM];
__device__ __align__(256) bf16  g_h1  [NQ*DFFN];
__device__ __align__(256) bf16  g_woa  [NLAY*384*256];
__device__ __align__(256) float g_boa  [NLAY*384];
__device__ __align__(256) bf16  g_wval [NLAY*256*256];
__device__ __align__(256) bf16  g_wout [NLAY*256*256];
__device__ __align__(256) bf16  g_wg   [NLAY*2048*256];  // interleaved W1/W3
__device__ __align__(256) float g_bg   [NLAY*2048];
__device__ __align__(256) bf16  g_w2   [NLAY*256*DFFN];

// ---------------- PTX helpers --------------------------------------------
__device__ __forceinline__ uint32_t smem_u32(const void* p) {
    uint32_t a;
    asm("{ .reg .u64 t; cvta.to.shared.u64 t, %1; cvt.u32.u64 %0, t; }"
        : "=r"(a) : "l"(p));
    return a;
}
#define CPASYNC16(saddr, gptr) \
    asm volatile("cp.async.cg.shared.global [%0], [%1], 16;" \
                 :: "r"(saddr), "l"(gptr))
#define CPASYNC_COMMIT() asm volatile("cp.async.commit_group;" ::: "memory")
#define CPASYNC_WAIT(n)  asm volatile("cp.async.wait_group %0;" :: "n"(n) : "memory")
#define LDSM4(d0,d1,d2,d3,addr) \
    asm volatile("ldmatrix.sync.aligned.m8n8.x4.shared.b16 {%0,%1,%2,%3}, [%4];" \
                 : "=r"(d0),"=r"(d1),"=r"(d2),"=r"(d3) : "r"(addr))
#define MMA16816(c, a, b0, b1) \
    asm volatile("mma.sync.aligned.m16n8k16.row.col.f32.bf16.bf16.f32 " \
                 "{%0,%1,%2,%3},{%4,%5,%6,%7},{%8,%9},{%0,%1,%2,%3};" \
                 : "+f"((c)[0]),"+f"((c)[1]),"+f"((c)[2]),"+f"((c)[3]) \
                 : "r"((a)[0]),"r"((a)[1]),"r"((a)[2]),"r"((a)[3]), \
                   "r"(b0),"r"(b1))
#define SWZ128(off) ((off) ^ (((off) >> 3) & 0x70))

__device__ __forceinline__ uint32_t pack_bf2(float a, float b) {
    __nv_bfloat162 h = __floats2bfloat162_rn(a, b);
    return *reinterpret_cast<uint32_t*>(&h);
}

// ================= bf16 tensor-core GEMM =====================================
// C[M,Nc] = A[M,K] @ B[Nc,K]^T + bias     (bf16 in, fp32 accumulate)
// EPI 0: C = v                      (BOUT: bf16 / fp32 out)
// EPI 1: C[f32] += ls[n]*v          (in-place residual)
// EPI 4: GLU: h1[m, n/2] = silu(v_even) * v_odd   (bf16 out, width Nc/2)
// EPI 5: merged val|oa: tiles 0-1 -> (A,B,bias,Cv,Nc=256); tiles 2-4 ->
//        (A2,B2,bias2,Cv2,Nc=384). bf16 out both.
#define STAGE_BYTES 32768
#define SMEM_TOTAL_GEMM (3*STAGE_BYTES)

template<int EPI, bool BOUT>
__global__ void __launch_bounds__(256, 2)
hgemm(int Nc, int K,
      const bf16* __restrict__ A, const bf16* __restrict__ B,
      const float* __restrict__ bias, void* __restrict__ Cv,
      const float* __restrict__ ls,
      const bf16* __restrict__ A2, const bf16* __restrict__ B2,
      const float* __restrict__ bias2, void* __restrict__ Cv2)
{
    extern __shared__ uint8_t dsm[];
    const uint32_t s0 = smem_u32(dsm);

    const int tid = threadIdx.x;
    const int lane = tid & 31, wid = tid >> 5;
    const int warp_m = wid >> 2, warp_n = wid & 3;   // 2 x 4
    const int bn = blockIdx.x, bm = blockIdx.y;
    const int NCH = K >> 6;

    // EPI5 source/dest selection
    const bf16* Ause = A;  const bf16* Buse = B;
    const float* biasuse = bias;
    void* Cuse = Cv;
    int NcU = Nc, bnl = bn;
    if (EPI == 5 && bn >= 2) {
        Ause = A2; Buse = B2; biasuse = bias2; Cuse = Cv2;
        NcU = 384; bnl = bn - 2;
    }

    const bf16* Ag = Ause + (size_t)(bm * 128) * K;
    const bf16* Bg = Buse + (size_t)(bnl * 128) * K;

    auto issue = [&](int c, int s) {
        uint32_t sa = s0 + s * STAGE_BYTES;
        uint32_t sb = sa + 16384;
        const bf16* Agp = Ag + c * 64;
        const bf16* Bgp = Bg + c * 64;
        #pragma unroll
        for (int j = 0; j < 4; j++) {
            int idx = tid + 256 * j;
            int row = idx >> 3, q = idx & 7;
            CPASYNC16(sa + SWZ128(row * 128 + q * 16),
                      Agp + (size_t)row * K + q * 8);
        }
        #pragma unroll
        for (int j = 0; j < 4; j++) {
            int idx = tid + 256 * j;
            int row = idx >> 3, q = idx & 7;
            CPASYNC16(sb + SWZ128(row * 128 + q * 16),
                      Bgp + (size_t)row * K + q * 8);
        }
        CPASYNC_COMMIT();
    };

    float acc[4][4][4];
    #pragma unroll
    for (int i = 0; i < 4; i++)
        #pragma unroll
        for (int j = 0; j < 4; j++)
            #pragma unroll
            for (int k = 0; k < 4; k++) acc[i][j][k] = 0.f;

    const int mat = lane >> 3, r8 = lane & 7;

    issue(0, 0);
    issue(1, 1);
    int s = 0;
    for (int c = 0; c < NCH; c++) {
        if (c + 1 < NCH) { CPASYNC_WAIT(1); } else { CPASYNC_WAIT(0); }
        __syncthreads();
        if (c + 2 < NCH) issue(c + 2, (s + 2) % 3);

        uint32_t sa = s0 + s * STAGE_BYTES;
        uint32_t sb = sa + 16384;
        #pragma unroll
        for (int ks = 0; ks < 4; ks++) {
            uint32_t a[4][4], bfr[4][2];
            #pragma unroll
            for (int mt = 0; mt < 4; mt++) {
                int row = warp_m * 64 + mt * 16 + (mat & 1) * 8 + r8;
                int kb  = ks * 32 + (mat >> 1) * 16;
                LDSM4(a[mt][0], a[mt][1], a[mt][2], a[mt][3],
                      sa + SWZ128(row * 128 + kb));
            }
            #pragma unroll
            for (int np = 0; np < 2; np++) {
                int nrow = warp_n * 32 + np * 16 + (mat >> 1) * 8 + r8;
                int kb   = ks * 32 + (mat & 1) * 16;
                uint32_t t0, t1, t2, t3;
                LDSM4(t0, t1, t2, t3, sb + SWZ128(nrow * 128 + kb));
                bfr[np*2+0][0] = t0; bfr[np*2+0][1] = t1;
                bfr[np*2+1][0] = t2; bfr[np*2+1][1] = t3;
            }
            #pragma unroll
            for (int mt = 0; mt < 4; mt++)
                #pragma unroll
                for (int nt = 0; nt < 4; nt++)
                    MMA16816(acc[mt][nt], a[mt], bfr[nt][0], bfr[nt][1]);
        }
        s = (s + 1) % 3;
    }

    // ---------------- epilogue ----------------
    const int g  = lane >> 2, tg = lane & 3;
    const int rbase = bm * 128 + warp_m * 64;
    const int cbase = bnl * 128 + warp_n * 32;

    #pragma unroll
    for (int mt = 0; mt < 4; mt++) {
        #pragma unroll
        for (int nt = 0; nt < 4; nt++) {
            int col = cbase + nt * 8 + tg * 2;
            float2 bs2 = *(const float2*)(biasuse + col);
            int r0 = rbase + mt * 16 + g;
            float v00 = acc[mt][nt][0] + bs2.x, v01 = acc[mt][nt][1] + bs2.y;
            float v10 = acc[mt][nt][2] + bs2.x, v11 = acc[mt][nt][3] + bs2.y;

            if (EPI == 4) {
                int j = col >> 1;
                int ncout = Nc >> 1;
                float g0 = (v00 / (1.f + __expf(-v00))) * v01;
                float g1 = (v10 / (1.f + __expf(-v10))) * v11;
                bf16* Cb = (bf16*)Cuse;
                Cb[(size_t)r0 * ncout + j]       = __float2bfloat16(g0);
                Cb[(size_t)(r0 + 8) * ncout + j] = __float2bfloat16(g1);
            } else {
                size_t i0 = (size_t)r0 * NcU + col;
                size_t i1 = (size_t)(r0 + 8) * NcU + col;
                if (EPI == 1) {
                    float2 ls2 = *(const float2*)(ls + col);
                    float* Cf = (float*)Cuse;
                    float2 q0 = *(float2*)(Cf + i0);
                    float2 q1 = *(float2*)(Cf + i1);
                    q0.x += ls2.x * v00; q0.y += ls2.y * v01;
                    q1.x += ls2.x * v10; q1.y += ls2.y * v11;
                    *(float2*)(Cf + i0) = q0;
                    *(float2*)(Cf + i1) = q1;
                } else if (!BOUT && EPI != 5) {
                    float* Cf = (float*)Cuse;
                    *(float2*)(Cf + i0) = make_float2(v00, v01);
                    *(float2*)(Cf + i1) = make_float2(v10, v11);
                } else {
                    bf16* Cb = (bf16*)Cuse;
                    *(uint32_t*)(Cb + i0) = pack_bf2(v00, v01);
                    *(uint32_t*)(Cb + i1) = pack_bf2(v10, v11);
                }
            }
        }
    }
}

// ---------------- weight prep ----------------
__global__ void f2bf(const float* __restrict__ in, bf16* __restrict__ out, int n) {
    for (int i = blockIdx.x * blockDim.x + threadIdx.x; i < n;
         i += gridDim.x * blockDim.x)
        out[i] = __float2bfloat16(in[i]);
}

__global__ void build_oa(const float* __restrict__ Woff, const float* __restrict__ Wattn,
                         const float* __restrict__ boff, const float* __restrict__ battn,
                         bf16* __restrict__ woa, float* __restrict__ boa)
{
    const int total = NLAY * 384 * 256;
    for (int i = blockIdx.x * blockDim.x + threadIdx.x; i < total;
         i += gridDim.x * blockDim.x) {
        int layer = i / (384 * 256);
        int rem = i - layer * 384 * 256;
        int r = rem >> 8, k = rem & 255;
        float v = (r < 256) ? Woff[layer * 65536 + r * 256 + k]
                            : Wattn[layer * 32768 + (r - 256) * 256 + k];
        woa[i] = __float2bfloat16(v);
    }
    const int tb = NLAY * 384;
    for (int i = blockIdx.x * blockDim.x + threadIdx.x; i < tb;
         i += gridDim.x * blockDim.x) {
        int layer = i / 384, r = i - layer * 384;
        boa[i] = (r < 256) ? boff[layer * 256 + r] : battn[layer * 128 + (r - 256)];
    }
}

__global__ void build_glu(const float* __restrict__ W1, const float* __restrict__ W3,
                          const float* __restrict__ b1, const float* __restrict__ b3,
                          bf16* __restrict__ wg, float* __restrict__ bg)
{
    const int total = NLAY * 2048 * 256;
    for (int i = blockIdx.x * blockDim.x + threadIdx.x; i < total;
         i += gridDim.x * blockDim.x) {
        int layer = i / (2048 * 256);
        int rem = i - layer * 2048 * 256;
        int r = rem >> 8, k = rem & 255;
        int j = r >> 1, sel = r & 1;
        const float* Wsrc = sel ? W3 : W1;
        wg[i] = __float2bfloat16(Wsrc[(size_t)layer * DFFN * 256 + j * 256 + k]);
    }
    const int tb = NLAY * 2048;
    for (int i = blockIdx.x * blockDim.x + threadIdx.x; i < tb;
         i += gridDim.x * blockDim.x) {
        int layer = i / 2048, r = i - layer * 2048;
        int j = r >> 1, sel = r & 1;
        bg[i] = sel ? b3[layer * DFFN + j] : b1[layer * DFFN + j];
    }
}

// ---------------- all-level transpose (one launch) --------------------------
struct Ptrs8 { const float* p[8]; };   // [t*4+lvl], t=0 src, t=1 pos

__global__ void __launch_bounds__(256)
transpose_all(Ptrs8 ps, const float* __restrict__ le,
              float* __restrict__ dq, float* __restrict__ dp)
{
    __shared__ float tile[32][33];
    int p0 = blockIdx.x * 32;              // global token within batch
    int d0 = blockIdx.y * 32;
    int bz = blockIdx.z;                   // b*2 + t
    int b = bz >> 1, t = bz & 1;
    int tx = threadIdx.x, ty = threadIdx.y;

    int lvl = (p0 >= 21504) ? 3 : (p0 >= 20480) ? 2 : (p0 >= 16384) ? 1 : 0;
    int HW  = c_LW[lvl] * c_LW[lvl];
    int loc = p0 - c_LS[lvl];

    const float* s = ps.p[t * 4 + lvl] + ((size_t)b * DIM + d0) * HW + loc;
    #pragma unroll
    for (int i = ty; i < 32; i += 8)
        tile[i][tx] = s[(size_t)i * HW + tx];
    __syncthreads();
    float* dst = t ? dp : dq;
    #pragma unroll
    for (int i = ty; i < 32; i += 8) {
        float v = tile[tx][i];
        if (t) v += le[lvl * DIM + d0 + tx];
        dst[((size_t)b * NTOK + p0 + i) * DIM + d0 + tx] = v;
    }
}

__global__ void __launch_bounds__(256)
rms_kernel(const float* __restrict__ x, const float* __restrict__ g,
           const float* __restrict__ posf, bf16* __restrict__ out_n,
           bf16* __restrict__ out_qin)
{
    int warp = threadIdx.x >> 5, lane = threadIdx.x & 31;
    int row  = blockIdx.x * 8 + warp;
    const float* xr = x + (size_t)row * DIM;

    float4 v0 = *(const float4*)(xr + lane * 4);
    float4 v1 = *(const float4*)(xr + 128 + lane * 4);
    float s = v0.x*v0.x + v0.y*v0.y + v0.z*v0.z + v0.w*v0.w
            + v1.x*v1.x + v1.y*v1.y + v1.z*v1.z + v1.w*v1.w;
    #pragma unroll
    for (int o = 16; o; o >>= 1) s += __shfl_xor_sync(0xffffffffu, s, o);
    float scale = rsqrtf(s * (1.0f / 256.0f) + 1e-6f);

    float4 ga = *(const float4*)(g + lane * 4);
    float4 gb = *(const float4*)(g + 128 + lane * 4);
    float n0x = v0.x*scale*ga.x, n0y = v0.y*scale*ga.y;
    float n0z = v0.z*scale*ga.z, n0w = v0.w*scale*ga.w;
    float n1x = v1.x*scale*gb.x, n1y = v1.y*scale*gb.y;
    float n1z = v1.z*scale*gb.z, n1w = v1.w*scale*gb.w;

    bf16* nr = out_n + (size_t)row * DIM;
    *(uint2*)(nr + lane * 4)       = make_uint2(pack_bf2(n0x, n0y), pack_bf2(n0z, n0w));
    *(uint2*)(nr + 128 + lane * 4) = make_uint2(pack_bf2(n1x, n1y), pack_bf2(n1z, n1w));

    if (out_qin) {
        const float* pr = posf + (size_t)row * DIM;
        float4 p0 = *(const float4*)(pr + lane * 4);
        float4 p1 = *(const float4*)(pr + 128 + lane * 4);
        bf16* qr = out_qin + (size_t)row * DIM;
        *(uint2*)(qr + lane * 4) =
            make_uint2(pack_bf2(n0x + p0.x, n0y + p0.y), pack_bf2(n0z + p0.z, n0w + p0.w));
        *(uint2*)(qr + 128 + lane * 4) =
            make_uint2(pack_bf2(n1x + p1.x, n1y + p1.y), pack_bf2(n1z + p1.z, n1w + p1.w));
    }
}

// ---------------- deformable sampling (bf16 oa) -----------------------------
__global__ void __launch_bounds__(256)
msda_kernel(const bf16* __restrict__ oa, const bf16* __restrict__ value,
            bf16* __restrict__ samp)
{
    int row  = blockIdx.x;
    int h    = threadIdx.x >> 5;
    int lane = threadIdx.x & 31;
    int ch   = lane & 15;
    int half = lane >> 4;
    int b = row / NTOK;
    int n = row - b * NTOK;

    int lvl = (n >= 21504) ? 3 : (n >= 20480) ? 2 : (n >= 16384) ? 1 : 0;
    int Wq  = c_LW[lvl];
    int li  = n - c_LS[lvl];
    int iy  = li / Wq, ix = li - iy * Wq;
    float refx = (ix + 0.5f) / (float)Wq;
    float refy = (iy + 0.5f) / (float)Wq;

    const bf16* al = oa + (size_t)row * 384 + 256 + h * 16;
    float lg[16];
    float m = -1e30f;
    #pragma unroll
    for (int j = 0; j < 8; j++) {
        float2 f = __bfloat1622float2(((const __nv_bfloat162*)al)[j]);
        lg[2*j] = f.x; lg[2*j+1] = f.y;
        m = fmaxf(m, fmaxf(f.x, f.y));
    }
    float s = 0.f;
    #pragma unroll
    for (int j = 0; j < 16; j++) { lg[j] = __expf(lg[j] - m); s += lg[j]; }
    float inv = 1.f / s;

    const __nv_bfloat162* op = (const __nv_bfloat162*)(oa + (size_t)row * 384 + h * 32);
    const __nv_bfloat162* vb =
        (const __nv_bfloat162*)(value + ((size_t)b * NTOK) * 256 + h * 32) + ch;
    float accx = 0.f, accy = 0.f;

    #pragma unroll
    for (int j = 0; j < 8; j++) {
        int p  = j * 2 + half;
        int l  = p >> 2;
        int Wl = c_LW[l], st = c_LS[l];
        float fW = (float)Wl;
        float2 o2 = __bfloat1622float2(op[p]);
        float xx = (refx + o2.x / fW) * fW - 0.5f;
        float yy = (refy + o2.y / fW) * fW - 0.5f;
        float x0f = floorf(xx), y0f = floorf(yy);
        int x0 = (int)x0f, y0 = (int)y0f;
        float fx = xx - x0f, fy = yy - y0f;
        float aw  = lg[p] * inv;
        float w00 = (1.f - fx) * (1.f - fy) * aw;
        float w10 = fx * (1.f - fy) * aw;
        float w01 = (1.f - fx) * fy * aw;
        float w11 = fx * fy * aw;
        bool vx0 = (x0 >= 0)     && (x0 < Wl);
        bool vx1 = (x0 + 1 >= 0) && (x0 + 1 < Wl);
        bool vy0 = (y0 >= 0)     && (y0 < Wl);
        bool vy1 = (y0 + 1 >= 0) && (y0 + 1 < Wl);
        if (vx0 && vy0) {
            float2 f = __bfloat1622float2(vb[(size_t)(st + y0 * Wl + x0) * 128]);
            accx += w00 * f.x; accy += w00 * f.y;
        }
        if (vx1 && vy0) {
            float2 f = __bfloat1622float2(vb[(size_t)(st + y0 * Wl + x0 + 1) * 128]);
            accx += w10 * f.x; accy += w10 * f.y;
        }
        if (vx0 && vy1) {
            float2 f = __bfloat1622float2(vb[(size_t)(st + (y0 + 1) * Wl + x0) * 128]);
            accx += w01 * f.x; accy += w01 * f.y;
        }
        if (vx1 && vy1) {
            float2 f = __bfloat1622float2(vb[(size_t)(st + (y0 + 1) * Wl + x0 + 1) * 128]);
            accx += w11 * f.x; accy += w11 * f.y;
        }
    }
    accx += __shfl_xor_sync(0xffffffffu, accx, 16);
    accy += __shfl_xor_sync(0xffffffffu, accy, 16);
    if (half == 0) {
        uint32_t* sp = (uint32_t*)(samp + (size_t)row * 256 + h * 32);
        sp[ch] = pack_bf2(accx, accy);
    }
}

__global__ void write_out(const float* __restrict__ q, float* __restrict__ out,
                          int out_size)
{
    for (int i = blockIdx.x * blockDim.x + threadIdx.x; i < out_size;
         i += gridDim.x * blockDim.x) {
        float v;
        if (i < QOUT) v = q[i];
        else { int j = i - QOUT; v = (j < 12) ? c_tail[j] : 0.f; }
        out[i] = v;
    }
}

// =============================== launcher ====================================
extern "C" void kernel_launch(void* const* d_in, const int* in_sizes, int n_in,
                              void* d_out, int out_size)
{
    (void)n_in;
    const float* src[4];
    const float* pos[4];
    bool interleaved = (in_sizes[1] == in_sizes[0]);
    for (int i = 0; i < 4; i++) {
        if (interleaved) { src[i] = (const float*)d_in[2*i];
                           pos[i] = (const float*)d_in[2*i+1]; }
        else             { src[i] = (const float*)d_in[i];
                           pos[i] = (const float*)d_in[4+i]; }
    }
    const float* level_embed = (const float*)d_in[8];
    const float* W_off  = (const float*)d_in[9];
    const float* b_off  = (const float*)d_in[10];
    const float* W_attn = (const float*)d_in[11];
    const float* b_attn = (const float*)d_in[12];
    const float* W_val  = (const float*)d_in[13];
    const float* b_val  = (const float*)d_in[14];
    const float* W_out  = (const float*)d_in[15];
    const float* b_out  = (const float*)d_in[16];
    const float* g_na   = (const float*)d_in[17];
    const float* g_nf   = (const float*)d_in[18];
    const float* ls_a   = (const float*)d_in[19];
    const float* ls_f   = (const float*)d_in[20];
    const float* W1     = (const float*)d_in[21];
    const float* b1     = (const float*)d_in[22];
    const float* W3     = (const float*)d_in[23];
    const float* b3     = (const float*)d_in[24];
    const float* W2     = (const float*)d_in[25];
    const float* b2     = (const float*)d_in[26];

    float *q, *posf, *boa, *bg;
    bf16 *nbuf, *qin, *val, *oab, *sampb, *h1;
    bf16 *woa, *wval, *wout, *wg, *w2;
    cudaGetSymbolAddress((void**)&q,     g_q);
    cudaGetSymbolAddress((void**)&posf,  g_posf);
    cudaGetSymbolAddress((void**)&nbuf,  g_n);
    cudaGetSymbolAddress((void**)&qin,   g_qin);
    cudaGetSymbolAddress((void**)&val,   g_val);
    cudaGetSymbolAddress((void**)&oab,   g_oa);
    cudaGetSymbolAddress((void**)&sampb, g_samp);
    cudaGetSymbolAddress((void**)&h1,    g_h1);
    cudaGetSymbolAddress((void**)&woa,   g_woa);
    cudaGetSymbolAddress((void**)&boa,   g_boa);
    cudaGetSymbolAddress((void**)&wval,  g_wval);
    cudaGetSymbolAddress((void**)&wout,  g_wout);
    cudaGetSymbolAddress((void**)&wg,    g_wg);
    cudaGetSymbolAddress((void**)&bg,    g_bg);
    cudaGetSymbolAddress((void**)&w2,    g_w2);

    cudaFuncSetAttribute((const void*)hgemm<1,false>, cudaFuncAttributeMaxDynamicSharedMemorySize, SMEM_TOTAL_GEMM);
    cudaFuncSetAttribute((const void*)hgemm<4,true >, cudaFuncAttributeMaxDynamicSharedMemorySize, SMEM_TOTAL_GEMM);
    cudaFuncSetAttribute((const void*)hgemm<5,true >, cudaFuncAttributeMaxDynamicSharedMemorySize, SMEM_TOTAL_GEMM);

    Ptrs8 ps;
    for (int l = 0; l < 4; l++) { ps.p[l] = src[l]; ps.p[4 + l] = pos[l]; }

    const int MT = NQ / 128;                  // 340 row tiles
    dim3 g2(2, MT), g5(5, MT), g16(16, MT);
    const int SB = SMEM_TOTAL_GEMM;

    // Launch order arranged so the 6th launch of the correctness run is the
    // merged projection GEMM (ncu -s 5 -c 1 then captures a real GEMM).
    // L0: all transposes in one kernel
    transpose_all<<<dim3(NTOK / 32, DIM / 32, BATCH * 2), dim3(32, 8)>>>(
        ps, level_embed, q, posf);

    for (int i = 0; i < NLAY; i++) {
        // L1 (layer 0): pre-attn norm
        rms_kernel<<<NQ / 8, 256>>>(q, g_na + i * DIM, posf, nbuf, qin);
        if (i == 0) {
            build_oa<<<1024, 256>>>(W_off, W_attn, b_off, b_attn, woa, boa);  // L2
            f2bf<<<1024, 256>>>(W_val, wval, NLAY*256*256);                   // L3
            f2bf<<<1024, 256>>>(W_out, wout, NLAY*256*256);                   // L4
        }
        // L5 (layer 0): merged val + off/attn projections   <- profiled
        hgemm<5,true><<<g5, 256, SB>>>(256, 256,
            nbuf, wval + (size_t)i*65536, b_val + i*256, val, nullptr,
            qin,  woa  + (size_t)i*98304, boa + i*384, oab);
        msda_kernel<<<NQ, 256>>>(oab, val, sampb);
        hgemm<1,false><<<g2, 256, SB>>>(256, 256, sampb, wout + (size_t)i*65536,
                                        b_out + i*256, q, ls_a + i*256,
                                        nullptr, nullptr, nullptr, nullptr);
        rms_kernel<<<NQ / 8, 256>>>(q, g_nf + i * DIM, nullptr, nbuf, nullptr);
        if (i == 0) {
            build_glu<<<2048, 256>>>(W1, W3, b1, b3, wg, bg);
            f2bf<<<1024, 256>>>(W2, w2, NLAY*256*DFFN);
        }
        hgemm<4,true ><<<g16, 256, SB>>>(2048, 256, nbuf, wg + (size_t)i*524288,
                                         bg + i*2048, h1, nullptr,
                                         nullptr, nullptr, nullptr, nullptr);
        hgemm<1,false><<<g2, 256, SB>>>(256, DFFN, h1, w2 + (size_t)i*262144,
                                        b2 + i*256, q, ls_f + i*256,
                                        nullptr, nullptr, nullptr, nullptr);
    }

    write_out<<<2048, 256>>>(q, (float*)d_out, out_size);
}